// round 8
// baseline (speedup 1.0000x reference)
#include <cuda_runtime.h>
#include <cuda_fp16.h>
#include <math.h>

#define N_NODES 50000
#define N_EDGES 800000

// Scratch (device globals — allocation-free per harness rules)
__device__ int   g_degi[N_NODES];
__device__ int   g_off[N_NODES];
__device__ int   g_cursor[N_NODES];
__device__ int   g_bflag[64];
__device__ int   g_bpref[64];
__device__ int   g_esrc[N_EDGES];       // CSR payload: src node of each in-edge of n
__device__ float g_dinv[N_NODES];
__device__ __align__(16) __half g_th[N_NODES * 64];   // t = x @ W1 (fp16)
__device__ __align__(16) float  g_agg[N_NODES * 64];  // normalized aggregation
__device__ __align__(16) __half g_Ph[N_NODES * 128];  // [A | B] per-node precompute (fp16)

// ---- packed f32x2 helpers (sm_103a FFMA2 — ptxas never auto-fuses these) ----
typedef unsigned long long ull;
__device__ __forceinline__ ull pack2(float v) {
    ull r; asm("mov.b64 %0, {%1,%2};" : "=l"(r) : "f"(v), "f"(v)); return r;
}
__device__ __forceinline__ ull packf2(float2 f) {
    ull r; asm("mov.b64 %0, {%1,%2};" : "=l"(r) : "f"(f.x), "f"(f.y)); return r;
}
__device__ __forceinline__ void unpack2(ull v, float& lo, float& hi) {
    asm("mov.b64 {%0,%1}, %2;" : "=f"(lo), "=f"(hi) : "l"(v));
}
__device__ __forceinline__ void fma2(ull& d, ull a, ull b) {
    asm("fma.rn.f32x2 %0, %1, %2, %0;" : "+l"(d) : "l"(a), "l"(b));
}
__device__ __forceinline__ ull add2(ull a, ull b) {
    ull r; asm("add.rn.f32x2 %0, %1, %2;" : "=l"(r) : "l"(a), "l"(b)); return r;
}
__device__ __forceinline__ unsigned int hadd2(unsigned int a, unsigned int b) {
    unsigned int r; asm("add.rn.f16x2 %0, %1, %2;" : "=r"(r) : "r"(a), "r"(b)); return r;
}
__device__ __forceinline__ ull h2tof2(unsigned int h) {
    __half2 hv = *reinterpret_cast<__half2*>(&h);
    float2 f = __half22float2(hv);
    return packf2(f);
}
__device__ __forceinline__ float2 h2f2(unsigned int h) {
    __half2 hv = *reinterpret_cast<__half2*>(&h);
    return __half22float2(hv);
}
__device__ __forceinline__ unsigned int f2h2(float lo, float hi) {
    __half2 p = __floats2half2_rn(lo, hi);
    return *(unsigned int*)&p;
}

__global__ void k_zero() {
    int i = blockIdx.x * blockDim.x + threadIdx.x;
    if (i < N_NODES) g_degi[i] = 0;
    if (i < 64) g_bflag[i] = 0;     // reset lookback flags each graph replay
}

__global__ void k_count(const int* __restrict__ dst) {
    int e = blockIdx.x * blockDim.x + threadIdx.x;
    if (e < N_EDGES) atomicAdd(&g_degi[dst[e]], 1);
}

// Single-pass decoupled-lookback exclusive scan of g_degi -> g_off,
// plus cursor init and dinv. 49 blocks of 1024 (all co-resident on 148 SMs).
__global__ void k_scan() {
    int tid = threadIdx.x;
    int b = blockIdx.x;
    int i = b * 1024 + tid;
    int v = (i < N_NODES) ? g_degi[i] : 0;
    int lane = tid & 31, wid = tid >> 5;
    int s = v;
#pragma unroll
    for (int o = 1; o < 32; o <<= 1) {
        int t = __shfl_up_sync(0xffffffffu, s, o);
        if (lane >= o) s += t;
    }
    __shared__ int ws[32];
    __shared__ int base_s;
    if (lane == 31) ws[wid] = s;
    __syncthreads();
    if (wid == 0) {
        int t = ws[lane];
        int ss = t;
#pragma unroll
        for (int o = 1; o < 32; o <<= 1) {
            int u = __shfl_up_sync(0xffffffffu, ss, o);
            if (lane >= o) ss += u;
        }
        ws[lane] = ss - t;
    }
    __syncthreads();
    int excl = ws[wid] + s - v;
    if (tid == 1023) {
        int tot = excl + v;              // block total (tail zeros included)
        int base = 0;
        if (b > 0) {
            while (atomicAdd(&g_bflag[b - 1], 0) == 0) { }
            base = g_bpref[b - 1];
        }
        g_bpref[b] = base + tot;
        __threadfence();
        atomicExch(&g_bflag[b], 1);
        base_s = base;
    }
    __syncthreads();
    if (i < N_NODES) {
        int o = excl + base_s;
        g_off[i] = o;
        g_cursor[i] = o;
        g_dinv[i] = rsqrtf((float)(g_degi[i] + 1));
    }
}

// CSR fill: store src id directly
__global__ void k_fill(const int* __restrict__ src, const int* __restrict__ dst) {
    int e = blockIdx.x * blockDim.x + threadIdx.x;
    if (e >= N_EDGES) return;
    int pos = atomicAdd(&g_cursor[dst[e]], 1);
    g_esrc[pos] = src[e];
}

// t = x @ W1 (fp16 out) — row-major tiles, float4 fills, 4-k chunked inner loop.
__global__ void k_mm1(const float* __restrict__ x, const float* __restrict__ W1) {
    __shared__ float sW[64 * 64];        // [k][j]
    __shared__ float sx[64 * 68];        // row-major [r][k], pitch 68 floats
    int tid = threadIdx.x;
    int row0 = blockIdx.x * 64;
    const float4* W4 = (const float4*)W1;
    float4* sW4s = (float4*)sW;
    for (int i = tid; i < 1024; i += 256) sW4s[i] = W4[i];
    const float4* x4 = (const float4*)x;
    float4* sx4 = (float4*)sx;
    for (int i = tid; i < 1024; i += 256) {
        int r = i >> 4, q = i & 15;
        int row = row0 + r;
        float4 v = (row < N_NODES) ? x4[row * 16 + q] : make_float4(0.f, 0.f, 0.f, 0.f);
        sx4[r * 17 + q] = v;
    }
    __syncthreads();
    int ty = tid >> 4, tx = tid & 15;
    ull c0a = 0, c0b = 0, c1a = 0, c1b = 0, c2a = 0, c2b = 0, c3a = 0, c3b = 0;
    const ulonglong2* sWu = (const ulonglong2*)sW;
    int rb = ty * 4;
#pragma unroll
    for (int k4 = 0; k4 < 16; k4++) {
        float4 xv0 = *(const float4*)&sx[(rb + 0) * 68 + k4 * 4];
        float4 xv1 = *(const float4*)&sx[(rb + 1) * 68 + k4 * 4];
        float4 xv2 = *(const float4*)&sx[(rb + 2) * 68 + k4 * 4];
        float4 xv3 = *(const float4*)&sx[(rb + 3) * 68 + k4 * 4];
        const float* p0 = &xv0.x;
        const float* p1 = &xv1.x;
        const float* p2 = &xv2.x;
        const float* p3 = &xv3.x;
#pragma unroll
        for (int j = 0; j < 4; j++) {
            int k = k4 * 4 + j;
            ulonglong2 w = sWu[k * 16 + tx];
            ull X0 = pack2(p0[j]), X1 = pack2(p1[j]), X2 = pack2(p2[j]), X3 = pack2(p3[j]);
            fma2(c0a, X0, w.x); fma2(c0b, X0, w.y);
            fma2(c1a, X1, w.x); fma2(c1b, X1, w.y);
            fma2(c2a, X2, w.x); fma2(c2b, X2, w.y);
            fma2(c3a, X3, w.x); fma2(c3b, X3, w.y);
        }
    }
    uint2* th2 = (uint2*)g_th;   // 16 uint2 per node row (64 halves)
    int row = row0 + rb;
    float lo, hi;
    uint2 u;
    unpack2(c0a, lo, hi); u.x = f2h2(lo, hi);
    unpack2(c0b, lo, hi); u.y = f2h2(lo, hi);
    if (row + 0 < N_NODES) th2[(row + 0) * 16 + tx] = u;
    unpack2(c1a, lo, hi); u.x = f2h2(lo, hi);
    unpack2(c1b, lo, hi); u.y = f2h2(lo, hi);
    if (row + 1 < N_NODES) th2[(row + 1) * 16 + tx] = u;
    unpack2(c2a, lo, hi); u.x = f2h2(lo, hi);
    unpack2(c2b, lo, hi); u.y = f2h2(lo, hi);
    if (row + 2 < N_NODES) th2[(row + 2) * 16 + tx] = u;
    unpack2(c3a, lo, hi); u.x = f2h2(lo, hi);
    unpack2(c3b, lo, hi); u.y = f2h2(lo, hi);
    if (row + 3 < N_NODES) th2[(row + 3) * 16 + tx] = u;
}

// CSR gather-reduce over fp16 t, no atomics. 16 threads/node, uint2 (4 cols) each.
__global__ void k_agg() {
    unsigned int gid = blockIdx.x * blockDim.x + threadIdx.x;
    unsigned int n = gid >> 4;
    int c = gid & 15;
    if (n >= N_NODES) return;
    const uint2* t2 = (const uint2*)g_th;
    float dn = g_dinv[n];
    uint2 u = t2[n * 16 + c];
    float2 s01 = h2f2(u.x), s23 = h2f2(u.y);
    float w2 = dn * dn;
    float4 acc = make_float4(s01.x * w2, s01.y * w2, s23.x * w2, s23.y * w2);
    int beg = g_off[n];
    int end = beg + g_degi[n];
#pragma unroll 4
    for (int j = beg; j < end; j++) {
        int s = g_esrc[j];             // broadcast across the 16-thread group
        float w = dn * g_dinv[s];
        uint2 uu = t2[s * 16 + c];
        float2 a01 = h2f2(uu.x), a23 = h2f2(uu.y);
        acc.x += a01.x * w; acc.y += a01.y * w;
        acc.z += a23.x * w; acc.w += a23.y * w;
    }
    ((float4*)g_agg)[n * 16 + c] = acc;
}

// h = relu(agg + b1); P = [h@Wm1[0:64]+bm1 | h@Wm1[64:128]] stored fp16
__global__ void k_mm2(const float* __restrict__ Wm1, const float* __restrict__ b1,
                      const float* __restrict__ bm1) {
    __shared__ float sW[64 * 128];  // [k][0:64]=Wm1[k], [k][64:128]=Wm1[64+k]
    __shared__ float sh[64 * 68];   // row-major [r][k], pitch 68
    int tid = threadIdx.x;
    int row0 = blockIdx.x * 64;
    const float4* Wm14 = (const float4*)Wm1;
    float4* sW4s = (float4*)sW;
    for (int i = tid; i < 2048; i += 256) {
        int k = i >> 5, jq = i & 31;
        float4 v = (jq < 16) ? Wm14[k * 16 + jq] : Wm14[(64 + k) * 16 + (jq - 16)];
        sW4s[i] = v;
    }
    const float4* agg4 = (const float4*)g_agg;
    const float4* b14 = (const float4*)b1;
    float4* sh4 = (float4*)sh;
    for (int i = tid; i < 1024; i += 256) {
        int r = i >> 4, q = i & 15;
        int row = row0 + r;
        float4 v = make_float4(0.f, 0.f, 0.f, 0.f);
        if (row < N_NODES) {
            float4 a = agg4[row * 16 + q];
            float4 b = b14[q];
            v.x = fmaxf(a.x + b.x, 0.f); v.y = fmaxf(a.y + b.y, 0.f);
            v.z = fmaxf(a.z + b.z, 0.f); v.w = fmaxf(a.w + b.w, 0.f);
        }
        sh4[r * 17 + q] = v;
    }
    __syncthreads();
    int ty = tid >> 4, tx = tid & 15;
    ull a0[4] = {0,0,0,0}, a1[4] = {0,0,0,0}, a2[4] = {0,0,0,0}, a3[4] = {0,0,0,0};
    const ulonglong2* sWu = (const ulonglong2*)sW;
    int rb = ty * 4;
#pragma unroll
    for (int k4 = 0; k4 < 16; k4++) {
        float4 hv0 = *(const float4*)&sh[(rb + 0) * 68 + k4 * 4];
        float4 hv1 = *(const float4*)&sh[(rb + 1) * 68 + k4 * 4];
        float4 hv2 = *(const float4*)&sh[(rb + 2) * 68 + k4 * 4];
        float4 hv3 = *(const float4*)&sh[(rb + 3) * 68 + k4 * 4];
        const float* p0 = &hv0.x;
        const float* p1 = &hv1.x;
        const float* p2 = &hv2.x;
        const float* p3 = &hv3.x;
#pragma unroll
        for (int j = 0; j < 4; j++) {
            int k = k4 * 4 + j;
            ulonglong2 wa = sWu[k * 32 + tx * 2 + 0];
            ulonglong2 wb = sWu[k * 32 + tx * 2 + 1];
            ull H0 = pack2(p0[j]), H1 = pack2(p1[j]), H2 = pack2(p2[j]), H3 = pack2(p3[j]);
            fma2(a0[0], H0, wa.x); fma2(a0[1], H0, wa.y); fma2(a0[2], H0, wb.x); fma2(a0[3], H0, wb.y);
            fma2(a1[0], H1, wa.x); fma2(a1[1], H1, wa.y); fma2(a1[2], H1, wb.x); fma2(a1[3], H1, wb.y);
            fma2(a2[0], H2, wa.x); fma2(a2[1], H2, wa.y); fma2(a2[2], H2, wb.x); fma2(a2[3], H2, wb.y);
            fma2(a3[0], H3, wa.x); fma2(a3[1], H3, wa.y); fma2(a3[2], H3, wb.x); fma2(a3[3], H3, wb.y);
        }
    }
    if (tx < 8) {  // fold bm1 into A half (added exactly once per edge)
        const ulonglong2* bmu = (const ulonglong2*)bm1;
        ulonglong2 ba = bmu[tx * 2 + 0];
        ulonglong2 bb = bmu[tx * 2 + 1];
        a0[0] = add2(a0[0], ba.x); a0[1] = add2(a0[1], ba.y); a0[2] = add2(a0[2], bb.x); a0[3] = add2(a0[3], bb.y);
        a1[0] = add2(a1[0], ba.x); a1[1] = add2(a1[1], ba.y); a1[2] = add2(a1[2], bb.x); a1[3] = add2(a1[3], bb.y);
        a2[0] = add2(a2[0], ba.x); a2[1] = add2(a2[1], ba.y); a2[2] = add2(a2[2], bb.x); a2[3] = add2(a2[3], bb.y);
        a3[0] = add2(a3[0], ba.x); a3[1] = add2(a3[1], ba.y); a3[2] = add2(a3[2], bb.x); a3[3] = add2(a3[3], bb.y);
    }
    uint4* P4 = (uint4*)g_Ph;
    int row = row0 + rb;
    ull* rows[4] = {a0, a1, a2, a3};
#pragma unroll
    for (int rr = 0; rr < 4; rr++) {
        if (row + rr >= N_NODES) break;
        float lo, hi;
        uint4 u;
        unpack2(rows[rr][0], lo, hi); u.x = f2h2(lo, hi);
        unpack2(rows[rr][1], lo, hi); u.y = f2h2(lo, hi);
        unpack2(rows[rr][2], lo, hi); u.z = f2h2(lo, hi);
        unpack2(rows[rr][3], lo, hi); u.w = f2h2(lo, hi);
        P4[(row + rr) * 16 + tx] = u;   // 8 cols starting at 8*tx
    }
}

// per-edge: hidden = relu(A[src] + B[dst] + ea@We); out = sigmoid(hidden . Wm2 + bm2)
// A+B summed in fp16 (1 HADD2 per half2), single conversion of the sum.
__global__ void k_edge(const int* __restrict__ src, const int* __restrict__ dst,
                       const float* __restrict__ ea, const float* __restrict__ Wm1,
                       const float* __restrict__ Wm2, const float* __restrict__ bm2,
                       float* __restrict__ out) {
    __shared__ ull sWe[16 * 32];  // Wm1 rows 128..143: [k][col-pair j2]
    __shared__ float sW2[64];
    __shared__ float sb2;
    int tid = threadIdx.x;
    for (int i = tid; i < 512; i += 256) {
        int k = i >> 5, j2 = i & 31;
        const float2* wrow = (const float2*)(Wm1 + (128 + k) * 64);
        sWe[i] = packf2(wrow[j2]);
    }
    if (tid < 64) sW2[tid] = Wm2[tid];
    if (tid == 0) sb2 = bm2[0];
    __syncthreads();
    unsigned int e = blockIdx.x * blockDim.x + tid;
    if (e >= N_EDGES) return;
    int s = src[e], d = dst[e];
    const uint4* PsA = (const uint4*)(g_Ph + s * 128);        // A half: 8 uint4
    const uint4* PdB = (const uint4*)(g_Ph + d * 128 + 64);   // B half: 8 uint4
    ull ek2[16];
    {
        const float4* ea4 = (const float4*)(ea + (size_t)e * 16);
#pragma unroll
        for (int q = 0; q < 4; q++) {
            float4 v = ea4[q];
            ek2[4 * q + 0] = pack2(v.x); ek2[4 * q + 1] = pack2(v.y);
            ek2[4 * q + 2] = pack2(v.z); ek2[4 * q + 3] = pack2(v.w);
        }
    }
    float acc = 0.f;
#pragma unroll
    for (int jg8 = 0; jg8 < 8; jg8++) {   // 8 cols per iteration
        uint4 au = PsA[jg8];
        uint4 bu = PdB[jg8];
        ull v0 = h2tof2(hadd2(au.x, bu.x));
        ull v1 = h2tof2(hadd2(au.y, bu.y));
        ull v2 = h2tof2(hadd2(au.z, bu.z));
        ull v3 = h2tof2(hadd2(au.w, bu.w));
#pragma unroll
        for (int k = 0; k < 16; k++) {
            const ull* w = &sWe[k * 32 + jg8 * 4];
            fma2(v0, ek2[k], w[0]);
            fma2(v1, ek2[k], w[1]);
            fma2(v2, ek2[k], w[2]);
            fma2(v3, ek2[k], w[3]);
        }
        float f0, f1, f2, f3, f4, f5, f6, f7;
        unpack2(v0, f0, f1); unpack2(v1, f2, f3);
        unpack2(v2, f4, f5); unpack2(v3, f6, f7);
        f0 = fmaxf(f0, 0.f); f1 = fmaxf(f1, 0.f); f2 = fmaxf(f2, 0.f); f3 = fmaxf(f3, 0.f);
        f4 = fmaxf(f4, 0.f); f5 = fmaxf(f5, 0.f); f6 = fmaxf(f6, 0.f); f7 = fmaxf(f7, 0.f);
        const float* w2 = &sW2[jg8 * 8];
        acc += f0 * w2[0] + f1 * w2[1] + f2 * w2[2] + f3 * w2[3]
             + f4 * w2[4] + f5 * w2[5] + f6 * w2[6] + f7 * w2[7];
    }
    out[e] = 1.f / (1.f + __expf(-(acc + sb2)));
}

extern "C" void kernel_launch(void* const* d_in, const int* in_sizes, int n_in,
                              void* d_out, int out_size) {
    const float* x   = (const float*)d_in[0];
    const int*   src = (const int*)d_in[1];
    const int*   dst = (const int*)d_in[2];
    const float* ea  = (const float*)d_in[3];
    const float* W1  = (const float*)d_in[4];
    const float* b1  = (const float*)d_in[5];
    const float* Wm1 = (const float*)d_in[6];
    const float* bm1 = (const float*)d_in[7];
    const float* Wm2 = (const float*)d_in[8];
    const float* bm2 = (const float*)d_in[9];
    float* out = (float*)d_out;
    (void)in_sizes; (void)n_in; (void)out_size;

    const int NB_SCAN = (N_NODES + 1023) / 1024;  // 49

    k_zero<<<(N_NODES + 255) / 256, 256>>>();
    k_count<<<(N_EDGES + 255) / 256, 256>>>(dst);
    k_mm1<<<(N_NODES + 63) / 64, 256>>>(x, W1);   // launch #3
    k_scan<<<NB_SCAN, 1024>>>();
    k_fill<<<(N_EDGES + 255) / 256, 256>>>(src, dst);
    k_agg<<<(N_NODES * 16 + 255) / 256, 256>>>();
    k_mm2<<<(N_NODES + 63) / 64, 256>>>(Wm1, b1, bm1);
    k_edge<<<(N_EDGES + 255) / 256, 256>>>(src, dst, ea, Wm1, Wm2, bm2, out);
}

// round 9
// speedup vs baseline: 1.2373x; 1.2373x over previous
#include <cuda_runtime.h>
#include <cuda_fp16.h>
#include <math.h>

#define N_NODES 50000
#define N_EDGES 800000

// Scratch (device globals — allocation-free per harness rules)
__device__ int   g_degi[N_NODES];
__device__ int   g_off[N_NODES];
__device__ int   g_cursor[N_NODES];
__device__ int   g_bsum[64];
__device__ int   g_esrc[N_EDGES];       // CSR payload: src node of each in-edge of n
__device__ float g_dinv[N_NODES];
__device__ __align__(16) __half g_th[N_NODES * 64];   // t = x @ W1 (fp16)
__device__ __align__(16) float  g_agg[N_NODES * 64];  // normalized aggregation
__device__ __align__(16) __half g_Ph[N_NODES * 128];  // [A | B] per-node precompute (fp16)

// ---- packed f32x2 helpers (sm_103a FFMA2 — ptxas never auto-fuses these) ----
typedef unsigned long long ull;
__device__ __forceinline__ ull pack2(float v) {
    ull r; asm("mov.b64 %0, {%1,%2};" : "=l"(r) : "f"(v), "f"(v)); return r;
}
__device__ __forceinline__ ull packf2(float2 f) {
    ull r; asm("mov.b64 %0, {%1,%2};" : "=l"(r) : "f"(f.x), "f"(f.y)); return r;
}
__device__ __forceinline__ void unpack2(ull v, float& lo, float& hi) {
    asm("mov.b64 {%0,%1}, %2;" : "=f"(lo), "=f"(hi) : "l"(v));
}
__device__ __forceinline__ void fma2(ull& d, ull a, ull b) {
    asm("fma.rn.f32x2 %0, %1, %2, %0;" : "+l"(d) : "l"(a), "l"(b));
}
__device__ __forceinline__ ull add2(ull a, ull b) {
    ull r; asm("add.rn.f32x2 %0, %1, %2;" : "=l"(r) : "l"(a), "l"(b)); return r;
}
__device__ __forceinline__ unsigned int hadd2(unsigned int a, unsigned int b) {
    unsigned int r; asm("add.rn.f16x2 %0, %1, %2;" : "=r"(r) : "r"(a), "r"(b)); return r;
}
__device__ __forceinline__ ull h2tof2(unsigned int h) {
    __half2 hv = *reinterpret_cast<__half2*>(&h);
    float2 f = __half22float2(hv);
    return packf2(f);
}
__device__ __forceinline__ float2 h2f2(unsigned int h) {
    __half2 hv = *reinterpret_cast<__half2*>(&h);
    return __half22float2(hv);
}
__device__ __forceinline__ unsigned int f2h2(float lo, float hi) {
    __half2 p = __floats2half2_rn(lo, hi);
    return *(unsigned int*)&p;
}

__global__ void k_zero() {
    int i = blockIdx.x * blockDim.x + threadIdx.x;
    if (i < N_NODES) g_degi[i] = 0;
}

__global__ void k_count(const int* __restrict__ dst) {
    int e = blockIdx.x * blockDim.x + threadIdx.x;
    if (e < N_EDGES) atomicAdd(&g_degi[dst[e]], 1);
}

// ---- exclusive prefix scan over g_degi (50000) -> g_off: two small launches ----
__global__ void k_scan1() {
    int tid = threadIdx.x;
    int i = blockIdx.x * 1024 + tid;
    int v = (i < N_NODES) ? g_degi[i] : 0;
    int lane = tid & 31, wid = tid >> 5;
    int s = v;
#pragma unroll
    for (int o = 1; o < 32; o <<= 1) {
        int t = __shfl_up_sync(0xffffffffu, s, o);
        if (lane >= o) s += t;
    }
    __shared__ int ws[32];
    if (lane == 31) ws[wid] = s;
    __syncthreads();
    if (wid == 0) {
        int t = ws[lane];
        int ss = t;
#pragma unroll
        for (int o = 1; o < 32; o <<= 1) {
            int u = __shfl_up_sync(0xffffffffu, ss, o);
            if (lane >= o) ss += u;
        }
        ws[lane] = ss - t;
    }
    __syncthreads();
    int excl = ws[wid] + s - v;
    if (i < N_NODES) g_off[i] = excl;
    if (tid == 1023) g_bsum[blockIdx.x] = ws[31] + s;
}

// scan3: per-block base via redundant smem sum; init cursor; dinv (incl. self loop)
__global__ void k_scan3(int nb) {
    __shared__ int sb[64];
    __shared__ int base_s;
    int tid = threadIdx.x;
    if (tid < 64) sb[tid] = (tid < nb) ? g_bsum[tid] : 0;
    __syncthreads();
    if (tid == 0) {
        int b = 0;
        for (int j = 0; j < (int)blockIdx.x; j++) b += sb[j];
        base_s = b;
    }
    __syncthreads();
    int i = blockIdx.x * 1024 + tid;
    if (i >= N_NODES) return;
    int o = g_off[i] + base_s;
    g_off[i] = o;
    g_cursor[i] = o;
    g_dinv[i] = rsqrtf((float)(g_degi[i] + 1));
}

// CSR fill: store src id directly
__global__ void k_fill(const int* __restrict__ src, const int* __restrict__ dst) {
    int e = blockIdx.x * blockDim.x + threadIdx.x;
    if (e >= N_EDGES) return;
    int pos = atomicAdd(&g_cursor[dst[e]], 1);
    g_esrc[pos] = src[e];
}

// t = x @ W1 (fp16 out) — row-major tiles, float4 fills, 4-k chunked inner loop.
__global__ void k_mm1(const float* __restrict__ x, const float* __restrict__ W1) {
    __shared__ float sW[64 * 64];        // [k][j]
    __shared__ float sx[64 * 68];        // row-major [r][k], pitch 68 floats
    int tid = threadIdx.x;
    int row0 = blockIdx.x * 64;
    const float4* W4 = (const float4*)W1;
    float4* sW4s = (float4*)sW;
    for (int i = tid; i < 1024; i += 256) sW4s[i] = W4[i];
    const float4* x4 = (const float4*)x;
    float4* sx4 = (float4*)sx;
    for (int i = tid; i < 1024; i += 256) {
        int r = i >> 4, q = i & 15;
        int row = row0 + r;
        float4 v = (row < N_NODES) ? x4[row * 16 + q] : make_float4(0.f, 0.f, 0.f, 0.f);
        sx4[r * 17 + q] = v;
    }
    __syncthreads();
    int ty = tid >> 4, tx = tid & 15;
    ull c0a = 0, c0b = 0, c1a = 0, c1b = 0, c2a = 0, c2b = 0, c3a = 0, c3b = 0;
    const ulonglong2* sWu = (const ulonglong2*)sW;
    int rb = ty * 4;
#pragma unroll
    for (int k4 = 0; k4 < 16; k4++) {
        float4 xv0 = *(const float4*)&sx[(rb + 0) * 68 + k4 * 4];
        float4 xv1 = *(const float4*)&sx[(rb + 1) * 68 + k4 * 4];
        float4 xv2 = *(const float4*)&sx[(rb + 2) * 68 + k4 * 4];
        float4 xv3 = *(const float4*)&sx[(rb + 3) * 68 + k4 * 4];
        const float* p0 = &xv0.x;
        const float* p1 = &xv1.x;
        const float* p2 = &xv2.x;
        const float* p3 = &xv3.x;
#pragma unroll
        for (int j = 0; j < 4; j++) {
            int k = k4 * 4 + j;
            ulonglong2 w = sWu[k * 16 + tx];
            ull X0 = pack2(p0[j]), X1 = pack2(p1[j]), X2 = pack2(p2[j]), X3 = pack2(p3[j]);
            fma2(c0a, X0, w.x); fma2(c0b, X0, w.y);
            fma2(c1a, X1, w.x); fma2(c1b, X1, w.y);
            fma2(c2a, X2, w.x); fma2(c2b, X2, w.y);
            fma2(c3a, X3, w.x); fma2(c3b, X3, w.y);
        }
    }
    uint2* th2 = (uint2*)g_th;   // 16 uint2 per node row (64 halves)
    int row = row0 + rb;
    float lo, hi;
    uint2 u;
    unpack2(c0a, lo, hi); u.x = f2h2(lo, hi);
    unpack2(c0b, lo, hi); u.y = f2h2(lo, hi);
    if (row + 0 < N_NODES) th2[(row + 0) * 16 + tx] = u;
    unpack2(c1a, lo, hi); u.x = f2h2(lo, hi);
    unpack2(c1b, lo, hi); u.y = f2h2(lo, hi);
    if (row + 1 < N_NODES) th2[(row + 1) * 16 + tx] = u;
    unpack2(c2a, lo, hi); u.x = f2h2(lo, hi);
    unpack2(c2b, lo, hi); u.y = f2h2(lo, hi);
    if (row + 2 < N_NODES) th2[(row + 2) * 16 + tx] = u;
    unpack2(c3a, lo, hi); u.x = f2h2(lo, hi);
    unpack2(c3b, lo, hi); u.y = f2h2(lo, hi);
    if (row + 3 < N_NODES) th2[(row + 3) * 16 + tx] = u;
}

// CSR gather-reduce over fp16 t, no atomics. 16 threads/node, uint2 (4 cols) each.
__global__ void k_agg() {
    unsigned int gid = blockIdx.x * blockDim.x + threadIdx.x;
    unsigned int n = gid >> 4;
    int c = gid & 15;
    if (n >= N_NODES) return;
    const uint2* t2 = (const uint2*)g_th;
    float dn = g_dinv[n];
    uint2 u = t2[n * 16 + c];
    float2 s01 = h2f2(u.x), s23 = h2f2(u.y);
    float w2 = dn * dn;
    float4 acc = make_float4(s01.x * w2, s01.y * w2, s23.x * w2, s23.y * w2);
    int beg = g_off[n];
    int end = beg + g_degi[n];
#pragma unroll 4
    for (int j = beg; j < end; j++) {
        int s = g_esrc[j];             // broadcast across the 16-thread group
        float w = dn * g_dinv[s];
        uint2 uu = t2[s * 16 + c];
        float2 a01 = h2f2(uu.x), a23 = h2f2(uu.y);
        acc.x += a01.x * w; acc.y += a01.y * w;
        acc.z += a23.x * w; acc.w += a23.y * w;
    }
    ((float4*)g_agg)[n * 16 + c] = acc;
}

// h = relu(agg + b1); P = [h@Wm1[0:64]+bm1 | h@Wm1[64:128]] stored fp16
__global__ void k_mm2(const float* __restrict__ Wm1, const float* __restrict__ b1,
                      const float* __restrict__ bm1) {
    __shared__ float sW[64 * 128];  // [k][0:64]=Wm1[k], [k][64:128]=Wm1[64+k]
    __shared__ float sh[64 * 68];   // row-major [r][k], pitch 68
    int tid = threadIdx.x;
    int row0 = blockIdx.x * 64;
    const float4* Wm14 = (const float4*)Wm1;
    float4* sW4s = (float4*)sW;
    for (int i = tid; i < 2048; i += 256) {
        int k = i >> 5, jq = i & 31;
        float4 v = (jq < 16) ? Wm14[k * 16 + jq] : Wm14[(64 + k) * 16 + (jq - 16)];
        sW4s[i] = v;
    }
    const float4* agg4 = (const float4*)g_agg;
    const float4* b14 = (const float4*)b1;
    float4* sh4 = (float4*)sh;
    for (int i = tid; i < 1024; i += 256) {
        int r = i >> 4, q = i & 15;
        int row = row0 + r;
        float4 v = make_float4(0.f, 0.f, 0.f, 0.f);
        if (row < N_NODES) {
            float4 a = agg4[row * 16 + q];
            float4 b = b14[q];
            v.x = fmaxf(a.x + b.x, 0.f); v.y = fmaxf(a.y + b.y, 0.f);
            v.z = fmaxf(a.z + b.z, 0.f); v.w = fmaxf(a.w + b.w, 0.f);
        }
        sh4[r * 17 + q] = v;
    }
    __syncthreads();
    int ty = tid >> 4, tx = tid & 15;
    ull a0[4] = {0,0,0,0}, a1[4] = {0,0,0,0}, a2[4] = {0,0,0,0}, a3[4] = {0,0,0,0};
    const ulonglong2* sWu = (const ulonglong2*)sW;
    int rb = ty * 4;
#pragma unroll
    for (int k4 = 0; k4 < 16; k4++) {
        float4 hv0 = *(const float4*)&sh[(rb + 0) * 68 + k4 * 4];
        float4 hv1 = *(const float4*)&sh[(rb + 1) * 68 + k4 * 4];
        float4 hv2 = *(const float4*)&sh[(rb + 2) * 68 + k4 * 4];
        float4 hv3 = *(const float4*)&sh[(rb + 3) * 68 + k4 * 4];
        const float* p0 = &hv0.x;
        const float* p1 = &hv1.x;
        const float* p2 = &hv2.x;
        const float* p3 = &hv3.x;
#pragma unroll
        for (int j = 0; j < 4; j++) {
            int k = k4 * 4 + j;
            ulonglong2 wa = sWu[k * 32 + tx * 2 + 0];
            ulonglong2 wb = sWu[k * 32 + tx * 2 + 1];
            ull H0 = pack2(p0[j]), H1 = pack2(p1[j]), H2 = pack2(p2[j]), H3 = pack2(p3[j]);
            fma2(a0[0], H0, wa.x); fma2(a0[1], H0, wa.y); fma2(a0[2], H0, wb.x); fma2(a0[3], H0, wb.y);
            fma2(a1[0], H1, wa.x); fma2(a1[1], H1, wa.y); fma2(a1[2], H1, wb.x); fma2(a1[3], H1, wb.y);
            fma2(a2[0], H2, wa.x); fma2(a2[1], H2, wa.y); fma2(a2[2], H2, wb.x); fma2(a2[3], H2, wb.y);
            fma2(a3[0], H3, wa.x); fma2(a3[1], H3, wa.y); fma2(a3[2], H3, wb.x); fma2(a3[3], H3, wb.y);
        }
    }
    if (tx < 8) {  // fold bm1 into A half (added exactly once per edge)
        const ulonglong2* bmu = (const ulonglong2*)bm1;
        ulonglong2 ba = bmu[tx * 2 + 0];
        ulonglong2 bb = bmu[tx * 2 + 1];
        a0[0] = add2(a0[0], ba.x); a0[1] = add2(a0[1], ba.y); a0[2] = add2(a0[2], bb.x); a0[3] = add2(a0[3], bb.y);
        a1[0] = add2(a1[0], ba.x); a1[1] = add2(a1[1], ba.y); a1[2] = add2(a1[2], bb.x); a1[3] = add2(a1[3], bb.y);
        a2[0] = add2(a2[0], ba.x); a2[1] = add2(a2[1], ba.y); a2[2] = add2(a2[2], bb.x); a2[3] = add2(a2[3], bb.y);
        a3[0] = add2(a3[0], ba.x); a3[1] = add2(a3[1], ba.y); a3[2] = add2(a3[2], bb.x); a3[3] = add2(a3[3], bb.y);
    }
    uint4* P4 = (uint4*)g_Ph;
    int row = row0 + rb;
    ull* rows[4] = {a0, a1, a2, a3};
#pragma unroll
    for (int rr = 0; rr < 4; rr++) {
        if (row + rr >= N_NODES) break;
        float lo, hi;
        uint4 u;
        unpack2(rows[rr][0], lo, hi); u.x = f2h2(lo, hi);
        unpack2(rows[rr][1], lo, hi); u.y = f2h2(lo, hi);
        unpack2(rows[rr][2], lo, hi); u.z = f2h2(lo, hi);
        unpack2(rows[rr][3], lo, hi); u.w = f2h2(lo, hi);
        P4[(row + rr) * 16 + tx] = u;   // 8 cols starting at 8*tx
    }
}

// per-edge: hidden = relu(A[src] + B[dst] + ea@We); out = sigmoid(hidden . Wm2 + bm2)
// A+B summed in fp16 (1 HADD2 per half2), single conversion of the sum.
__global__ void k_edge(const int* __restrict__ src, const int* __restrict__ dst,
                       const float* __restrict__ ea, const float* __restrict__ Wm1,
                       const float* __restrict__ Wm2, const float* __restrict__ bm2,
                       float* __restrict__ out) {
    __shared__ ull sWe[16 * 32];  // Wm1 rows 128..143: [k][col-pair j2]
    __shared__ float sW2[64];
    __shared__ float sb2;
    int tid = threadIdx.x;
    for (int i = tid; i < 512; i += 256) {
        int k = i >> 5, j2 = i & 31;
        const float2* wrow = (const float2*)(Wm1 + (128 + k) * 64);
        sWe[i] = packf2(wrow[j2]);
    }
    if (tid < 64) sW2[tid] = Wm2[tid];
    if (tid == 0) sb2 = bm2[0];
    __syncthreads();
    unsigned int e = blockIdx.x * blockDim.x + tid;
    if (e >= N_EDGES) return;
    int s = src[e], d = dst[e];
    const uint4* PsA = (const uint4*)(g_Ph + s * 128);        // A half: 8 uint4
    const uint4* PdB = (const uint4*)(g_Ph + d * 128 + 64);   // B half: 8 uint4
    ull ek2[16];
    {
        const float4* ea4 = (const float4*)(ea + (size_t)e * 16);
#pragma unroll
        for (int q = 0; q < 4; q++) {
            float4 v = ea4[q];
            ek2[4 * q + 0] = pack2(v.x); ek2[4 * q + 1] = pack2(v.y);
            ek2[4 * q + 2] = pack2(v.z); ek2[4 * q + 3] = pack2(v.w);
        }
    }
    float acc = 0.f;
#pragma unroll
    for (int jg8 = 0; jg8 < 8; jg8++) {   // 8 cols per iteration
        uint4 au = PsA[jg8];
        uint4 bu = PdB[jg8];
        ull v0 = h2tof2(hadd2(au.x, bu.x));
        ull v1 = h2tof2(hadd2(au.y, bu.y));
        ull v2 = h2tof2(hadd2(au.z, bu.z));
        ull v3 = h2tof2(hadd2(au.w, bu.w));
#pragma unroll
        for (int k = 0; k < 16; k++) {
            const ull* w = &sWe[k * 32 + jg8 * 4];
            fma2(v0, ek2[k], w[0]);
            fma2(v1, ek2[k], w[1]);
            fma2(v2, ek2[k], w[2]);
            fma2(v3, ek2[k], w[3]);
        }
        float f0, f1, f2, f3, f4, f5, f6, f7;
        unpack2(v0, f0, f1); unpack2(v1, f2, f3);
        unpack2(v2, f4, f5); unpack2(v3, f6, f7);
        f0 = fmaxf(f0, 0.f); f1 = fmaxf(f1, 0.f); f2 = fmaxf(f2, 0.f); f3 = fmaxf(f3, 0.f);
        f4 = fmaxf(f4, 0.f); f5 = fmaxf(f5, 0.f); f6 = fmaxf(f6, 0.f); f7 = fmaxf(f7, 0.f);
        const float* w2 = &sW2[jg8 * 8];
        acc += f0 * w2[0] + f1 * w2[1] + f2 * w2[2] + f3 * w2[3]
             + f4 * w2[4] + f5 * w2[5] + f6 * w2[6] + f7 * w2[7];
    }
    out[e] = 1.f / (1.f + __expf(-(acc + sb2)));
}

extern "C" void kernel_launch(void* const* d_in, const int* in_sizes, int n_in,
                              void* d_out, int out_size) {
    const float* x   = (const float*)d_in[0];
    const int*   src = (const int*)d_in[1];
    const int*   dst = (const int*)d_in[2];
    const float* ea  = (const float*)d_in[3];
    const float* W1  = (const float*)d_in[4];
    const float* b1  = (const float*)d_in[5];
    const float* Wm1 = (const float*)d_in[6];
    const float* bm1 = (const float*)d_in[7];
    const float* Wm2 = (const float*)d_in[8];
    const float* bm2 = (const float*)d_in[9];
    float* out = (float*)d_out;
    (void)in_sizes; (void)n_in; (void)out_size;

    const int NB_SCAN = (N_NODES + 1023) / 1024;  // 49

    k_zero<<<(N_NODES + 255) / 256, 256>>>();
    k_count<<<(N_EDGES + 255) / 256, 256>>>(dst);
    k_scan1<<<NB_SCAN, 1024>>>();
    k_mm1<<<(N_NODES + 63) / 64, 256>>>(x, W1);   // launch #4 → ncu capture slot
    k_scan3<<<NB_SCAN, 1024>>>(NB_SCAN);
    k_fill<<<(N_EDGES + 255) / 256, 256>>>(src, dst);
    k_agg<<<(N_NODES * 16 + 255) / 256, 256>>>();
    k_mm2<<<(N_NODES + 63) / 64, 256>>>(Wm1, b1, bm1);
    k_edge<<<(N_EDGES + 255) / 256, 256>>>(src, dst, ea, Wm1, Wm2, bm2, out);
}

// round 10
// speedup vs baseline: 1.2670x; 1.0240x over previous
#include <cuda_runtime.h>
#include <cuda_fp16.h>
#include <math.h>

#define N_NODES 50000
#define N_EDGES 800000

// Scratch (device globals — allocation-free per harness rules)
__device__ int   g_degi[N_NODES];
__device__ int   g_off[N_NODES];
__device__ int   g_cursor[N_NODES];
__device__ int   g_bsum[64];
__device__ int   g_esrc[N_EDGES];       // CSR payload: src node of each in-edge of n
__device__ float g_dinv[N_NODES];
__device__ __align__(16) __half g_th[N_NODES * 64];   // t = x @ W1 (fp16)
__device__ __align__(16) float  g_agg[N_NODES * 64];  // normalized aggregation
__device__ __align__(16) __half g_Ph[N_NODES * 128];  // [A | B] per-node precompute (fp16)

// ---- packed f32x2 helpers (sm_103a FFMA2 — ptxas never auto-fuses these) ----
typedef unsigned long long ull;
__device__ __forceinline__ ull pack2(float v) {
    ull r; asm("mov.b64 %0, {%1,%2};" : "=l"(r) : "f"(v), "f"(v)); return r;
}
__device__ __forceinline__ ull packf2(float2 f) {
    ull r; asm("mov.b64 %0, {%1,%2};" : "=l"(r) : "f"(f.x), "f"(f.y)); return r;
}
__device__ __forceinline__ void unpack2(ull v, float& lo, float& hi) {
    asm("mov.b64 {%0,%1}, %2;" : "=f"(lo), "=f"(hi) : "l"(v));
}
__device__ __forceinline__ void fma2(ull& d, ull a, ull b) {
    asm("fma.rn.f32x2 %0, %1, %2, %0;" : "+l"(d) : "l"(a), "l"(b));
}
__device__ __forceinline__ ull add2(ull a, ull b) {
    ull r; asm("add.rn.f32x2 %0, %1, %2;" : "=l"(r) : "l"(a), "l"(b)); return r;
}
__device__ __forceinline__ unsigned int hadd2(unsigned int a, unsigned int b) {
    unsigned int r; asm("add.rn.f16x2 %0, %1, %2;" : "=r"(r) : "r"(a), "r"(b)); return r;
}
__device__ __forceinline__ ull h2tof2(unsigned int h) {
    __half2 hv = *reinterpret_cast<__half2*>(&h);
    float2 f = __half22float2(hv);
    return packf2(f);
}
__device__ __forceinline__ float2 h2f2(unsigned int h) {
    __half2 hv = *reinterpret_cast<__half2*>(&h);
    return __half22float2(hv);
}
__device__ __forceinline__ unsigned int f2h2(float lo, float hi) {
    __half2 p = __floats2half2_rn(lo, hi);
    return *(unsigned int*)&p;
}

__global__ void k_count(const int* __restrict__ dst) {
    int e = blockIdx.x * blockDim.x + threadIdx.x;
    if (e < N_EDGES) atomicAdd(&g_degi[dst[e]], 1);
}

// ---- exclusive prefix scan over g_degi (50000) -> g_off: two small launches ----
__global__ void k_scan1() {
    int tid = threadIdx.x;
    int i = blockIdx.x * 1024 + tid;
    int v = (i < N_NODES) ? g_degi[i] : 0;
    int lane = tid & 31, wid = tid >> 5;
    int s = v;
#pragma unroll
    for (int o = 1; o < 32; o <<= 1) {
        int t = __shfl_up_sync(0xffffffffu, s, o);
        if (lane >= o) s += t;
    }
    __shared__ int ws[32];
    if (lane == 31) ws[wid] = s;
    __syncthreads();
    if (wid == 0) {
        int t = ws[lane];
        int ss = t;
#pragma unroll
        for (int o = 1; o < 32; o <<= 1) {
            int u = __shfl_up_sync(0xffffffffu, ss, o);
            if (lane >= o) ss += u;
        }
        ws[lane] = ss - t;
    }
    __syncthreads();
    int excl = ws[wid] + s - v;
    if (i < N_NODES) g_off[i] = excl;
    if (tid == 1023) g_bsum[blockIdx.x] = ws[31] + s;
}

// scan3: per-block base via redundant smem sum; init cursor; dinv (incl. self loop)
__global__ void k_scan3(int nb) {
    __shared__ int sb[64];
    __shared__ int base_s;
    int tid = threadIdx.x;
    if (tid < 64) sb[tid] = (tid < nb) ? g_bsum[tid] : 0;
    __syncthreads();
    if (tid == 0) {
        int b = 0;
        for (int j = 0; j < (int)blockIdx.x; j++) b += sb[j];
        base_s = b;
    }
    __syncthreads();
    int i = blockIdx.x * 1024 + tid;
    if (i >= N_NODES) return;
    int o = g_off[i] + base_s;
    g_off[i] = o;
    g_cursor[i] = o;
    g_dinv[i] = rsqrtf((float)(g_degi[i] + 1));
}

// CSR fill: store src id directly
__global__ void k_fill(const int* __restrict__ src, const int* __restrict__ dst) {
    int e = blockIdx.x * blockDim.x + threadIdx.x;
    if (e >= N_EDGES) return;
    int pos = atomicAdd(&g_cursor[dst[e]], 1);
    g_esrc[pos] = src[e];
}

// t = x @ W1 (fp16 out) — row-major tiles, float4 fills, 4-k chunked inner loop.
__global__ void k_mm1(const float* __restrict__ x, const float* __restrict__ W1) {
    __shared__ float sW[64 * 64];        // [k][j]
    __shared__ float sx[64 * 68];        // row-major [r][k], pitch 68 floats
    int tid = threadIdx.x;
    int row0 = blockIdx.x * 64;
    const float4* W4 = (const float4*)W1;
    float4* sW4s = (float4*)sW;
    for (int i = tid; i < 1024; i += 256) sW4s[i] = W4[i];
    const float4* x4 = (const float4*)x;
    float4* sx4 = (float4*)sx;
    for (int i = tid; i < 1024; i += 256) {
        int r = i >> 4, q = i & 15;
        int row = row0 + r;
        float4 v = (row < N_NODES) ? x4[row * 16 + q] : make_float4(0.f, 0.f, 0.f, 0.f);
        sx4[r * 17 + q] = v;
    }
    __syncthreads();
    int ty = tid >> 4, tx = tid & 15;
    ull c0a = 0, c0b = 0, c1a = 0, c1b = 0, c2a = 0, c2b = 0, c3a = 0, c3b = 0;
    const ulonglong2* sWu = (const ulonglong2*)sW;
    int rb = ty * 4;
#pragma unroll
    for (int k4 = 0; k4 < 16; k4++) {
        float4 xv0 = *(const float4*)&sx[(rb + 0) * 68 + k4 * 4];
        float4 xv1 = *(const float4*)&sx[(rb + 1) * 68 + k4 * 4];
        float4 xv2 = *(const float4*)&sx[(rb + 2) * 68 + k4 * 4];
        float4 xv3 = *(const float4*)&sx[(rb + 3) * 68 + k4 * 4];
        const float* p0 = &xv0.x;
        const float* p1 = &xv1.x;
        const float* p2 = &xv2.x;
        const float* p3 = &xv3.x;
#pragma unroll
        for (int j = 0; j < 4; j++) {
            int k = k4 * 4 + j;
            ulonglong2 w = sWu[k * 16 + tx];
            ull X0 = pack2(p0[j]), X1 = pack2(p1[j]), X2 = pack2(p2[j]), X3 = pack2(p3[j]);
            fma2(c0a, X0, w.x); fma2(c0b, X0, w.y);
            fma2(c1a, X1, w.x); fma2(c1b, X1, w.y);
            fma2(c2a, X2, w.x); fma2(c2b, X2, w.y);
            fma2(c3a, X3, w.x); fma2(c3b, X3, w.y);
        }
    }
    uint2* th2 = (uint2*)g_th;   // 16 uint2 per node row (64 halves)
    int row = row0 + rb;
    float lo, hi;
    uint2 u;
    unpack2(c0a, lo, hi); u.x = f2h2(lo, hi);
    unpack2(c0b, lo, hi); u.y = f2h2(lo, hi);
    if (row + 0 < N_NODES) th2[(row + 0) * 16 + tx] = u;
    unpack2(c1a, lo, hi); u.x = f2h2(lo, hi);
    unpack2(c1b, lo, hi); u.y = f2h2(lo, hi);
    if (row + 1 < N_NODES) th2[(row + 1) * 16 + tx] = u;
    unpack2(c2a, lo, hi); u.x = f2h2(lo, hi);
    unpack2(c2b, lo, hi); u.y = f2h2(lo, hi);
    if (row + 2 < N_NODES) th2[(row + 2) * 16 + tx] = u;
    unpack2(c3a, lo, hi); u.x = f2h2(lo, hi);
    unpack2(c3b, lo, hi); u.y = f2h2(lo, hi);
    if (row + 3 < N_NODES) th2[(row + 3) * 16 + tx] = u;
}

// CSR gather-reduce over fp16 t, no atomics. 16 threads/node, uint2 (4 cols) each.
__global__ void k_agg() {
    unsigned int gid = blockIdx.x * blockDim.x + threadIdx.x;
    unsigned int n = gid >> 4;
    int c = gid & 15;
    if (n >= N_NODES) return;
    const uint2* t2 = (const uint2*)g_th;
    float dn = g_dinv[n];
    uint2 u = t2[n * 16 + c];
    float2 s01 = h2f2(u.x), s23 = h2f2(u.y);
    float w2 = dn * dn;
    float4 acc = make_float4(s01.x * w2, s01.y * w2, s23.x * w2, s23.y * w2);
    int beg = g_off[n];
    int end = beg + g_degi[n];
#pragma unroll 4
    for (int j = beg; j < end; j++) {
        int s = g_esrc[j];             // broadcast across the 16-thread group
        float w = dn * g_dinv[s];
        uint2 uu = t2[s * 16 + c];
        float2 a01 = h2f2(uu.x), a23 = h2f2(uu.y);
        acc.x += a01.x * w; acc.y += a01.y * w;
        acc.z += a23.x * w; acc.w += a23.y * w;
    }
    ((float4*)g_agg)[n * 16 + c] = acc;
}

// h = relu(agg + b1); P = [h@Wm1[0:64]+bm1 | h@Wm1[64:128]] stored fp16
__global__ void k_mm2(const float* __restrict__ Wm1, const float* __restrict__ b1,
                      const float* __restrict__ bm1) {
    __shared__ float sW[64 * 128];  // [k][0:64]=Wm1[k], [k][64:128]=Wm1[64+k]
    __shared__ float sh[64 * 68];   // row-major [r][k], pitch 68
    int tid = threadIdx.x;
    int row0 = blockIdx.x * 64;
    const float4* Wm14 = (const float4*)Wm1;
    float4* sW4s = (float4*)sW;
    for (int i = tid; i < 2048; i += 256) {
        int k = i >> 5, jq = i & 31;
        float4 v = (jq < 16) ? Wm14[k * 16 + jq] : Wm14[(64 + k) * 16 + (jq - 16)];
        sW4s[i] = v;
    }
    const float4* agg4 = (const float4*)g_agg;
    const float4* b14 = (const float4*)b1;
    float4* sh4 = (float4*)sh;
    for (int i = tid; i < 1024; i += 256) {
        int r = i >> 4, q = i & 15;
        int row = row0 + r;
        float4 v = make_float4(0.f, 0.f, 0.f, 0.f);
        if (row < N_NODES) {
            float4 a = agg4[row * 16 + q];
            float4 b = b14[q];
            v.x = fmaxf(a.x + b.x, 0.f); v.y = fmaxf(a.y + b.y, 0.f);
            v.z = fmaxf(a.z + b.z, 0.f); v.w = fmaxf(a.w + b.w, 0.f);
        }
        sh4[r * 17 + q] = v;
    }
    __syncthreads();
    int ty = tid >> 4, tx = tid & 15;
    ull a0[4] = {0,0,0,0}, a1[4] = {0,0,0,0}, a2[4] = {0,0,0,0}, a3[4] = {0,0,0,0};
    const ulonglong2* sWu = (const ulonglong2*)sW;
    int rb = ty * 4;
#pragma unroll
    for (int k4 = 0; k4 < 16; k4++) {
        float4 hv0 = *(const float4*)&sh[(rb + 0) * 68 + k4 * 4];
        float4 hv1 = *(const float4*)&sh[(rb + 1) * 68 + k4 * 4];
        float4 hv2 = *(const float4*)&sh[(rb + 2) * 68 + k4 * 4];
        float4 hv3 = *(const float4*)&sh[(rb + 3) * 68 + k4 * 4];
        const float* p0 = &hv0.x;
        const float* p1 = &hv1.x;
        const float* p2 = &hv2.x;
        const float* p3 = &hv3.x;
#pragma unroll
        for (int j = 0; j < 4; j++) {
            int k = k4 * 4 + j;
            ulonglong2 wa = sWu[k * 32 + tx * 2 + 0];
            ulonglong2 wb = sWu[k * 32 + tx * 2 + 1];
            ull H0 = pack2(p0[j]), H1 = pack2(p1[j]), H2 = pack2(p2[j]), H3 = pack2(p3[j]);
            fma2(a0[0], H0, wa.x); fma2(a0[1], H0, wa.y); fma2(a0[2], H0, wb.x); fma2(a0[3], H0, wb.y);
            fma2(a1[0], H1, wa.x); fma2(a1[1], H1, wa.y); fma2(a1[2], H1, wb.x); fma2(a1[3], H1, wb.y);
            fma2(a2[0], H2, wa.x); fma2(a2[1], H2, wa.y); fma2(a2[2], H2, wb.x); fma2(a2[3], H2, wb.y);
            fma2(a3[0], H3, wa.x); fma2(a3[1], H3, wa.y); fma2(a3[2], H3, wb.x); fma2(a3[3], H3, wb.y);
        }
    }
    if (tx < 8) {  // fold bm1 into A half (added exactly once per edge)
        const ulonglong2* bmu = (const ulonglong2*)bm1;
        ulonglong2 ba = bmu[tx * 2 + 0];
        ulonglong2 bb = bmu[tx * 2 + 1];
        a0[0] = add2(a0[0], ba.x); a0[1] = add2(a0[1], ba.y); a0[2] = add2(a0[2], bb.x); a0[3] = add2(a0[3], bb.y);
        a1[0] = add2(a1[0], ba.x); a1[1] = add2(a1[1], ba.y); a1[2] = add2(a1[2], bb.x); a1[3] = add2(a1[3], bb.y);
        a2[0] = add2(a2[0], ba.x); a2[1] = add2(a2[1], ba.y); a2[2] = add2(a2[2], bb.x); a2[3] = add2(a2[3], bb.y);
        a3[0] = add2(a3[0], ba.x); a3[1] = add2(a3[1], ba.y); a3[2] = add2(a3[2], bb.x); a3[3] = add2(a3[3], bb.y);
    }
    uint4* P4 = (uint4*)g_Ph;
    int row = row0 + rb;
    ull* rows[4] = {a0, a1, a2, a3};
#pragma unroll
    for (int rr = 0; rr < 4; rr++) {
        if (row + rr >= N_NODES) break;
        float lo, hi;
        uint4 u;
        unpack2(rows[rr][0], lo, hi); u.x = f2h2(lo, hi);
        unpack2(rows[rr][1], lo, hi); u.y = f2h2(lo, hi);
        unpack2(rows[rr][2], lo, hi); u.z = f2h2(lo, hi);
        unpack2(rows[rr][3], lo, hi); u.w = f2h2(lo, hi);
        P4[(row + rr) * 16 + tx] = u;   // 8 cols starting at 8*tx
    }
}

// per-edge: hidden = relu(A[src] + B[dst] + ea@We); out = sigmoid(hidden . Wm2 + bm2)
// A+B summed in fp16 (1 HADD2 per half2), single conversion of the sum.
__global__ void k_edge(const int* __restrict__ src, const int* __restrict__ dst,
                       const float* __restrict__ ea, const float* __restrict__ Wm1,
                       const float* __restrict__ Wm2, const float* __restrict__ bm2,
                       float* __restrict__ out) {
    __shared__ ull sWe[16 * 32];  // Wm1 rows 128..143: [k][col-pair j2]
    __shared__ float sW2[64];
    __shared__ float sb2;
    int tid = threadIdx.x;
    for (int i = tid; i < 512; i += 256) {
        int k = i >> 5, j2 = i & 31;
        const float2* wrow = (const float2*)(Wm1 + (128 + k) * 64);
        sWe[i] = packf2(wrow[j2]);
    }
    if (tid < 64) sW2[tid] = Wm2[tid];
    if (tid == 0) sb2 = bm2[0];
    __syncthreads();
    unsigned int e = blockIdx.x * blockDim.x + tid;
    if (e >= N_EDGES) return;
    int s = src[e], d = dst[e];
    const uint4* PsA = (const uint4*)(g_Ph + s * 128);        // A half: 8 uint4
    const uint4* PdB = (const uint4*)(g_Ph + d * 128 + 64);   // B half: 8 uint4
    ull ek2[16];
    {
        const float4* ea4 = (const float4*)(ea + (size_t)e * 16);
#pragma unroll
        for (int q = 0; q < 4; q++) {
            float4 v = ea4[q];
            ek2[4 * q + 0] = pack2(v.x); ek2[4 * q + 1] = pack2(v.y);
            ek2[4 * q + 2] = pack2(v.z); ek2[4 * q + 3] = pack2(v.w);
        }
    }
    float acc = 0.f;
#pragma unroll
    for (int jg8 = 0; jg8 < 8; jg8++) {   // 8 cols per iteration
        uint4 au = PsA[jg8];
        uint4 bu = PdB[jg8];
        ull v0 = h2tof2(hadd2(au.x, bu.x));
        ull v1 = h2tof2(hadd2(au.y, bu.y));
        ull v2 = h2tof2(hadd2(au.z, bu.z));
        ull v3 = h2tof2(hadd2(au.w, bu.w));
#pragma unroll
        for (int k = 0; k < 16; k++) {
            const ull* w = &sWe[k * 32 + jg8 * 4];
            fma2(v0, ek2[k], w[0]);
            fma2(v1, ek2[k], w[1]);
            fma2(v2, ek2[k], w[2]);
            fma2(v3, ek2[k], w[3]);
        }
        float f0, f1, f2, f3, f4, f5, f6, f7;
        unpack2(v0, f0, f1); unpack2(v1, f2, f3);
        unpack2(v2, f4, f5); unpack2(v3, f6, f7);
        f0 = fmaxf(f0, 0.f); f1 = fmaxf(f1, 0.f); f2 = fmaxf(f2, 0.f); f3 = fmaxf(f3, 0.f);
        f4 = fmaxf(f4, 0.f); f5 = fmaxf(f5, 0.f); f6 = fmaxf(f6, 0.f); f7 = fmaxf(f7, 0.f);
        const float* w2 = &sW2[jg8 * 8];
        acc += f0 * w2[0] + f1 * w2[1] + f2 * w2[2] + f3 * w2[3]
             + f4 * w2[4] + f5 * w2[5] + f6 * w2[6] + f7 * w2[7];
    }
    out[e] = 1.f / (1.f + __expf(-(acc + sb2)));
}

extern "C" void kernel_launch(void* const* d_in, const int* in_sizes, int n_in,
                              void* d_out, int out_size) {
    const float* x   = (const float*)d_in[0];
    const int*   src = (const int*)d_in[1];
    const int*   dst = (const int*)d_in[2];
    const float* ea  = (const float*)d_in[3];
    const float* W1  = (const float*)d_in[4];
    const float* b1  = (const float*)d_in[5];
    const float* Wm1 = (const float*)d_in[6];
    const float* bm1 = (const float*)d_in[7];
    const float* Wm2 = (const float*)d_in[8];
    const float* bm2 = (const float*)d_in[9];
    float* out = (float*)d_out;
    (void)in_sizes; (void)n_in; (void)out_size;

    const int NB_SCAN = (N_NODES + 1023) / 1024;  // 49

    // One-time host-side setup (first call is the uncaptured correctness run;
    // no device memory is allocated here).
    static cudaStream_t s_side = nullptr;
    static cudaEvent_t  s_fork = nullptr, s_join = nullptr;
    static void* degi_ptr = nullptr;
    if (!s_side) {
        cudaStreamCreateWithFlags(&s_side, cudaStreamNonBlocking);
        cudaEventCreateWithFlags(&s_fork, cudaEventDisableTiming);
        cudaEventCreateWithFlags(&s_join, cudaEventDisableTiming);
        cudaGetSymbolAddress(&degi_ptr, g_degi);
    }

    // Fork: k_mm1 (independent of graph structure) runs on the side stream,
    // overlapping the CSR build chain on the main (capture) stream.
    cudaEventRecord(s_fork, 0);
    cudaStreamWaitEvent(s_side, s_fork, 0);
    k_mm1<<<(N_NODES + 63) / 64, 256, 0, s_side>>>(x, W1);
    cudaEventRecord(s_join, s_side);

    // Main stream: degree histogram -> scan -> CSR fill
    cudaMemsetAsync(degi_ptr, 0, N_NODES * sizeof(int), 0);
    k_count<<<(N_EDGES + 255) / 256, 256>>>(dst);
    k_scan1<<<NB_SCAN, 1024>>>();
    k_scan3<<<NB_SCAN, 1024>>>(NB_SCAN);
    k_fill<<<(N_EDGES + 255) / 256, 256>>>(src, dst);

    // Join: k_agg needs both k_mm1 (t) and k_fill (CSR)
    cudaStreamWaitEvent(0, s_join, 0);
    k_agg<<<(N_NODES * 16 + 255) / 256, 256>>>();
    k_mm2<<<(N_NODES + 63) / 64, 256>>>(Wm1, b1, bm1);
    k_edge<<<(N_EDGES + 255) / 256, 256>>>(src, dst, ea, Wm1, Wm2, bm2, out);
}

// round 11
// speedup vs baseline: 1.5857x; 1.2516x over previous
#include <cuda_runtime.h>
#include <cuda_fp16.h>
#include <math.h>

#define N_NODES 50000
#define N_EDGES 800000

// Scratch (device globals — allocation-free per harness rules)
__device__ int   g_degi[N_NODES];
__device__ int   g_off[N_NODES];
__device__ int   g_cursor[N_NODES];
__device__ int   g_bsum[64];
__device__ int   g_esrc[N_EDGES];       // CSR payload: src node of each in-edge of n
__device__ float g_dinv[N_NODES];
__device__ __align__(16) __half g_th[N_NODES * 64];   // t = x @ W1 (fp16)
__device__ __align__(16) float  g_agg[N_NODES * 64];  // normalized aggregation
__device__ __align__(16) __half g_Ph[N_NODES * 128];  // [A | B] per-node precompute (fp16)

// ---- packed f32x2 helpers (sm_103a FFMA2 — ptxas never auto-fuses these) ----
typedef unsigned long long ull;
__device__ __forceinline__ ull pack2(float v) {
    ull r; asm("mov.b64 %0, {%1,%2};" : "=l"(r) : "f"(v), "f"(v)); return r;
}
__device__ __forceinline__ ull packf2(float2 f) {
    ull r; asm("mov.b64 %0, {%1,%2};" : "=l"(r) : "f"(f.x), "f"(f.y)); return r;
}
__device__ __forceinline__ void unpack2(ull v, float& lo, float& hi) {
    asm("mov.b64 {%0,%1}, %2;" : "=f"(lo), "=f"(hi) : "l"(v));
}
__device__ __forceinline__ void fma2(ull& d, ull a, ull b) {
    asm("fma.rn.f32x2 %0, %1, %2, %0;" : "+l"(d) : "l"(a), "l"(b));
}
__device__ __forceinline__ ull add2(ull a, ull b) {
    ull r; asm("add.rn.f32x2 %0, %1, %2;" : "=l"(r) : "l"(a), "l"(b)); return r;
}
__device__ __forceinline__ unsigned int hadd2(unsigned int a, unsigned int b) {
    unsigned int r; asm("add.rn.f16x2 %0, %1, %2;" : "=r"(r) : "r"(a), "r"(b)); return r;
}
__device__ __forceinline__ ull h2tof2(unsigned int h) {
    __half2 hv = *reinterpret_cast<__half2*>(&h);
    float2 f = __half22float2(hv);
    return packf2(f);
}
__device__ __forceinline__ float2 h2f2(unsigned int h) {
    __half2 hv = *reinterpret_cast<__half2*>(&h);
    return __half22float2(hv);
}
__device__ __forceinline__ unsigned int f2h2(float lo, float hi) {
    __half2 p = __floats2half2_rn(lo, hi);
    return *(unsigned int*)&p;
}

__global__ void k_count(const int* __restrict__ dst) {
    int e = blockIdx.x * blockDim.x + threadIdx.x;
    if (e < N_EDGES) atomicAdd(&g_degi[dst[e]], 1);
}

// ---- exclusive prefix scan over g_degi (50000) -> g_off: two small launches ----
__global__ void k_scan1() {
    int tid = threadIdx.x;
    int i = blockIdx.x * 1024 + tid;
    int v = (i < N_NODES) ? g_degi[i] : 0;
    int lane = tid & 31, wid = tid >> 5;
    int s = v;
#pragma unroll
    for (int o = 1; o < 32; o <<= 1) {
        int t = __shfl_up_sync(0xffffffffu, s, o);
        if (lane >= o) s += t;
    }
    __shared__ int ws[32];
    if (lane == 31) ws[wid] = s;
    __syncthreads();
    if (wid == 0) {
        int t = ws[lane];
        int ss = t;
#pragma unroll
        for (int o = 1; o < 32; o <<= 1) {
            int u = __shfl_up_sync(0xffffffffu, ss, o);
            if (lane >= o) ss += u;
        }
        ws[lane] = ss - t;
    }
    __syncthreads();
    int excl = ws[wid] + s - v;
    if (i < N_NODES) g_off[i] = excl;
    if (tid == 1023) g_bsum[blockIdx.x] = ws[31] + s;
}

// scan3: per-block base via redundant smem sum; init cursor; dinv (incl. self loop)
__global__ void k_scan3(int nb) {
    __shared__ int sb[64];
    __shared__ int base_s;
    int tid = threadIdx.x;
    if (tid < 64) sb[tid] = (tid < nb) ? g_bsum[tid] : 0;
    __syncthreads();
    if (tid == 0) {
        int b = 0;
        for (int j = 0; j < (int)blockIdx.x; j++) b += sb[j];
        base_s = b;
    }
    __syncthreads();
    int i = blockIdx.x * 1024 + tid;
    if (i >= N_NODES) return;
    int o = g_off[i] + base_s;
    g_off[i] = o;
    g_cursor[i] = o;
    g_dinv[i] = rsqrtf((float)(g_degi[i] + 1));
}

// CSR fill: store src id directly
__global__ void k_fill(const int* __restrict__ src, const int* __restrict__ dst) {
    int e = blockIdx.x * blockDim.x + threadIdx.x;
    if (e >= N_EDGES) return;
    int pos = atomicAdd(&g_cursor[dst[e]], 1);
    g_esrc[pos] = src[e];
}

// t = x @ W1 (fp16 out) — row-major tiles, float4 fills, 4-k chunked inner loop.
__global__ void k_mm1(const float* __restrict__ x, const float* __restrict__ W1) {
    __shared__ float sW[64 * 64];        // [k][j]
    __shared__ float sx[64 * 68];        // row-major [r][k], pitch 68 floats
    int tid = threadIdx.x;
    int row0 = blockIdx.x * 64;
    const float4* W4 = (const float4*)W1;
    float4* sW4s = (float4*)sW;
    for (int i = tid; i < 1024; i += 256) sW4s[i] = W4[i];
    const float4* x4 = (const float4*)x;
    float4* sx4 = (float4*)sx;
    for (int i = tid; i < 1024; i += 256) {
        int r = i >> 4, q = i & 15;
        int row = row0 + r;
        float4 v = (row < N_NODES) ? x4[row * 16 + q] : make_float4(0.f, 0.f, 0.f, 0.f);
        sx4[r * 17 + q] = v;
    }
    __syncthreads();
    int ty = tid >> 4, tx = tid & 15;
    ull c0a = 0, c0b = 0, c1a = 0, c1b = 0, c2a = 0, c2b = 0, c3a = 0, c3b = 0;
    const ulonglong2* sWu = (const ulonglong2*)sW;
    int rb = ty * 4;
#pragma unroll
    for (int k4 = 0; k4 < 16; k4++) {
        float4 xv0 = *(const float4*)&sx[(rb + 0) * 68 + k4 * 4];
        float4 xv1 = *(const float4*)&sx[(rb + 1) * 68 + k4 * 4];
        float4 xv2 = *(const float4*)&sx[(rb + 2) * 68 + k4 * 4];
        float4 xv3 = *(const float4*)&sx[(rb + 3) * 68 + k4 * 4];
        const float* p0 = &xv0.x;
        const float* p1 = &xv1.x;
        const float* p2 = &xv2.x;
        const float* p3 = &xv3.x;
#pragma unroll
        for (int j = 0; j < 4; j++) {
            int k = k4 * 4 + j;
            ulonglong2 w = sWu[k * 16 + tx];
            ull X0 = pack2(p0[j]), X1 = pack2(p1[j]), X2 = pack2(p2[j]), X3 = pack2(p3[j]);
            fma2(c0a, X0, w.x); fma2(c0b, X0, w.y);
            fma2(c1a, X1, w.x); fma2(c1b, X1, w.y);
            fma2(c2a, X2, w.x); fma2(c2b, X2, w.y);
            fma2(c3a, X3, w.x); fma2(c3b, X3, w.y);
        }
    }
    uint2* th2 = (uint2*)g_th;   // 16 uint2 per node row (64 halves)
    int row = row0 + rb;
    float lo, hi;
    uint2 u;
    unpack2(c0a, lo, hi); u.x = f2h2(lo, hi);
    unpack2(c0b, lo, hi); u.y = f2h2(lo, hi);
    if (row + 0 < N_NODES) th2[(row + 0) * 16 + tx] = u;
    unpack2(c1a, lo, hi); u.x = f2h2(lo, hi);
    unpack2(c1b, lo, hi); u.y = f2h2(lo, hi);
    if (row + 1 < N_NODES) th2[(row + 1) * 16 + tx] = u;
    unpack2(c2a, lo, hi); u.x = f2h2(lo, hi);
    unpack2(c2b, lo, hi); u.y = f2h2(lo, hi);
    if (row + 2 < N_NODES) th2[(row + 2) * 16 + tx] = u;
    unpack2(c3a, lo, hi); u.x = f2h2(lo, hi);
    unpack2(c3b, lo, hi); u.y = f2h2(lo, hi);
    if (row + 3 < N_NODES) th2[(row + 3) * 16 + tx] = u;
}

// CSR gather-reduce over fp16 t, no atomics. 16 threads/node, uint2 (4 cols) each.
__global__ void k_agg() {
    unsigned int gid = blockIdx.x * blockDim.x + threadIdx.x;
    unsigned int n = gid >> 4;
    int c = gid & 15;
    if (n >= N_NODES) return;
    const uint2* t2 = (const uint2*)g_th;
    float dn = g_dinv[n];
    uint2 u = t2[n * 16 + c];
    float2 s01 = h2f2(u.x), s23 = h2f2(u.y);
    float w2 = dn * dn;
    float4 acc = make_float4(s01.x * w2, s01.y * w2, s23.x * w2, s23.y * w2);
    int beg = g_off[n];
    int end = beg + g_degi[n];
#pragma unroll 4
    for (int j = beg; j < end; j++) {
        int s = g_esrc[j];             // broadcast across the 16-thread group
        float w = dn * g_dinv[s];
        uint2 uu = t2[s * 16 + c];
        float2 a01 = h2f2(uu.x), a23 = h2f2(uu.y);
        acc.x += a01.x * w; acc.y += a01.y * w;
        acc.z += a23.x * w; acc.w += a23.y * w;
    }
    ((float4*)g_agg)[n * 16 + c] = acc;
}

// h = relu(agg + b1); P = [h@Wm1[0:64]+bm1 | h@Wm1[64:128]] stored fp16
__global__ void k_mm2(const float* __restrict__ Wm1, const float* __restrict__ b1,
                      const float* __restrict__ bm1) {
    __shared__ float sW[64 * 128];  // [k][0:64]=Wm1[k], [k][64:128]=Wm1[64+k]
    __shared__ float sh[64 * 68];   // row-major [r][k], pitch 68
    int tid = threadIdx.x;
    int row0 = blockIdx.x * 64;
    const float4* Wm14 = (const float4*)Wm1;
    float4* sW4s = (float4*)sW;
    for (int i = tid; i < 2048; i += 256) {
        int k = i >> 5, jq = i & 31;
        float4 v = (jq < 16) ? Wm14[k * 16 + jq] : Wm14[(64 + k) * 16 + (jq - 16)];
        sW4s[i] = v;
    }
    const float4* agg4 = (const float4*)g_agg;
    const float4* b14 = (const float4*)b1;
    float4* sh4 = (float4*)sh;
    for (int i = tid; i < 1024; i += 256) {
        int r = i >> 4, q = i & 15;
        int row = row0 + r;
        float4 v = make_float4(0.f, 0.f, 0.f, 0.f);
        if (row < N_NODES) {
            float4 a = agg4[row * 16 + q];
            float4 b = b14[q];
            v.x = fmaxf(a.x + b.x, 0.f); v.y = fmaxf(a.y + b.y, 0.f);
            v.z = fmaxf(a.z + b.z, 0.f); v.w = fmaxf(a.w + b.w, 0.f);
        }
        sh4[r * 17 + q] = v;
    }
    __syncthreads();
    int ty = tid >> 4, tx = tid & 15;
    ull a0[4] = {0,0,0,0}, a1[4] = {0,0,0,0}, a2[4] = {0,0,0,0}, a3[4] = {0,0,0,0};
    const ulonglong2* sWu = (const ulonglong2*)sW;
    int rb = ty * 4;
#pragma unroll
    for (int k4 = 0; k4 < 16; k4++) {
        float4 hv0 = *(const float4*)&sh[(rb + 0) * 68 + k4 * 4];
        float4 hv1 = *(const float4*)&sh[(rb + 1) * 68 + k4 * 4];
        float4 hv2 = *(const float4*)&sh[(rb + 2) * 68 + k4 * 4];
        float4 hv3 = *(const float4*)&sh[(rb + 3) * 68 + k4 * 4];
        const float* p0 = &hv0.x;
        const float* p1 = &hv1.x;
        const float* p2 = &hv2.x;
        const float* p3 = &hv3.x;
#pragma unroll
        for (int j = 0; j < 4; j++) {
            int k = k4 * 4 + j;
            ulonglong2 wa = sWu[k * 32 + tx * 2 + 0];
            ulonglong2 wb = sWu[k * 32 + tx * 2 + 1];
            ull H0 = pack2(p0[j]), H1 = pack2(p1[j]), H2 = pack2(p2[j]), H3 = pack2(p3[j]);
            fma2(a0[0], H0, wa.x); fma2(a0[1], H0, wa.y); fma2(a0[2], H0, wb.x); fma2(a0[3], H0, wb.y);
            fma2(a1[0], H1, wa.x); fma2(a1[1], H1, wa.y); fma2(a1[2], H1, wb.x); fma2(a1[3], H1, wb.y);
            fma2(a2[0], H2, wa.x); fma2(a2[1], H2, wa.y); fma2(a2[2], H2, wb.x); fma2(a2[3], H2, wb.y);
            fma2(a3[0], H3, wa.x); fma2(a3[1], H3, wa.y); fma2(a3[2], H3, wb.x); fma2(a3[3], H3, wb.y);
        }
    }
    if (tx < 8) {  // fold bm1 into A half (added exactly once per edge)
        const ulonglong2* bmu = (const ulonglong2*)bm1;
        ulonglong2 ba = bmu[tx * 2 + 0];
        ulonglong2 bb = bmu[tx * 2 + 1];
        a0[0] = add2(a0[0], ba.x); a0[1] = add2(a0[1], ba.y); a0[2] = add2(a0[2], bb.x); a0[3] = add2(a0[3], bb.y);
        a1[0] = add2(a1[0], ba.x); a1[1] = add2(a1[1], ba.y); a1[2] = add2(a1[2], bb.x); a1[3] = add2(a1[3], bb.y);
        a2[0] = add2(a2[0], ba.x); a2[1] = add2(a2[1], ba.y); a2[2] = add2(a2[2], bb.x); a2[3] = add2(a2[3], bb.y);
        a3[0] = add2(a3[0], ba.x); a3[1] = add2(a3[1], ba.y); a3[2] = add2(a3[2], bb.x); a3[3] = add2(a3[3], bb.y);
    }
    uint4* P4 = (uint4*)g_Ph;
    int row = row0 + rb;
    ull* rows[4] = {a0, a1, a2, a3};
#pragma unroll
    for (int rr = 0; rr < 4; rr++) {
        if (row + rr >= N_NODES) break;
        float lo, hi;
        uint4 u;
        unpack2(rows[rr][0], lo, hi); u.x = f2h2(lo, hi);
        unpack2(rows[rr][1], lo, hi); u.y = f2h2(lo, hi);
        unpack2(rows[rr][2], lo, hi); u.z = f2h2(lo, hi);
        unpack2(rows[rr][3], lo, hi); u.w = f2h2(lo, hi);
        P4[(row + rr) * 16 + tx] = u;   // 8 cols starting at 8*tx
    }
}

// per-edge via tensor cores: G = ea@We on HMMA (m16n8k16), epilogue in-register.
// Each warp owns 16 edges; block = 256 threads = 8 warps = 128 edges; grid = 6250.
__global__ void k_edge(const int* __restrict__ src, const int* __restrict__ dst,
                       const float* __restrict__ ea, const float* __restrict__ Wm1,
                       const float* __restrict__ Wm2, const float* __restrict__ bm2,
                       float* __restrict__ out) {
    __shared__ __align__(16) unsigned short sEA[128 * 16];   // ea tile fp16, pitch 16 halves
    __shared__ unsigned int sB0[8 * 32], sB1[8 * 32];        // B fragments per (tile, lane)
    __shared__ float sW2[64];
    __shared__ float sb2;
    int tid = threadIdx.x;
    int lane = tid & 31, w = tid >> 5;
    int g = lane >> 2, q = lane & 3;
    // --- B fragments for We = Wm1 rows 128..143 (k=16 x n=64), col-tile = tid>>5 ---
    {
        int coln = (tid >> 5) * 8 + g;     // n-column for this (tile, lane)
        int k0 = 2 * q;
        sB0[tid] = f2h2(Wm1[(128 + k0) * 64 + coln],     Wm1[(128 + k0 + 1) * 64 + coln]);
        sB1[tid] = f2h2(Wm1[(128 + k0 + 8) * 64 + coln], Wm1[(128 + k0 + 9) * 64 + coln]);
    }
    if (tid < 64) sW2[tid] = Wm2[tid];
    if (tid == 0) sb2 = bm2[0];
    // --- ea -> smem fp16: thread loads half a row (8 floats) ---
    {
        int eloc = tid >> 1, part = tid & 1;
        size_t e = (size_t)blockIdx.x * 128 + eloc;
        const float4* ea4 = (const float4*)(ea + e * 16) + part * 2;
        float4 v0 = ea4[0], v1 = ea4[1];
        unsigned int* d16 = (unsigned int*)&sEA[eloc * 16 + part * 8];
        d16[0] = f2h2(v0.x, v0.y); d16[1] = f2h2(v0.z, v0.w);
        d16[2] = f2h2(v1.x, v1.y); d16[3] = f2h2(v1.z, v1.w);
    }
    __syncthreads();
    // --- per-warp: 16 edges [wbase, wbase+16) ---
    int wbase = w * 16;
    int r0 = wbase + g, r1 = wbase + g + 8;          // this thread's two edge rows
    unsigned int ebase = blockIdx.x * 128;
    int e0 = ebase + r0, e1 = ebase + r1;
    int s0 = src[e0], d0n = dst[e0];
    int s1 = src[e1], d1n = dst[e1];
    // A fragments (rows r0/r1 of ea tile, halves 2q..2q+1 and 2q+8..2q+9)
    const unsigned int* EA32 = (const unsigned int*)sEA;   // 8 words per edge row
    unsigned int a0 = EA32[r0 * 8 + q];
    unsigned int a1 = EA32[r1 * 8 + q];
    unsigned int a2 = EA32[r0 * 8 + q + 4];
    unsigned int a3 = EA32[r1 * 8 + q + 4];
    const unsigned int* Ph32 = (const unsigned int*)g_Ph;  // 64 half2-words per node
    float acc0 = 0.f, acc1 = 0.f;
#pragma unroll
    for (int j = 0; j < 8; j++) {
        float c0 = 0.f, c1 = 0.f, c2 = 0.f, c3 = 0.f;
        asm volatile(
            "mma.sync.aligned.m16n8k16.row.col.f32.f16.f16.f32 "
            "{%0,%1,%2,%3}, {%4,%5,%6,%7}, {%8,%9}, {%0,%1,%2,%3};"
            : "+f"(c0), "+f"(c1), "+f"(c2), "+f"(c3)
            : "r"(a0), "r"(a1), "r"(a2), "r"(a3),
              "r"(sB0[j * 32 + lane]), "r"(sB1[j * 32 + lane]));
        // cols for this thread: jc = j*8 + 2q, jc+1  -> half2 word j*4+q
        int cw = j * 4 + q;
        unsigned int pa0 = Ph32[s0 * 64 + cw];          // A half (cols 0..63)
        unsigned int pb0 = Ph32[d0n * 64 + 32 + cw];    // B half (cols 64..127)
        unsigned int pa1 = Ph32[s1 * 64 + cw];
        unsigned int pb1 = Ph32[d1n * 64 + 32 + cw];
        float2 h0 = h2f2(hadd2(pa0, pb0));
        float2 h1 = h2f2(hadd2(pa1, pb1));
        c0 = fmaxf(c0 + h0.x, 0.f); c1 = fmaxf(c1 + h0.y, 0.f);
        c2 = fmaxf(c2 + h1.x, 0.f); c3 = fmaxf(c3 + h1.y, 0.f);
        float2 w2v = *(const float2*)&sW2[j * 8 + 2 * q];
        acc0 += c0 * w2v.x + c1 * w2v.y;
        acc1 += c2 * w2v.x + c3 * w2v.y;
    }
    // reduce across the 4 lanes sharing each edge row (lanes g*4 .. g*4+3)
    acc0 += __shfl_xor_sync(0xffffffffu, acc0, 1);
    acc0 += __shfl_xor_sync(0xffffffffu, acc0, 2);
    acc1 += __shfl_xor_sync(0xffffffffu, acc1, 1);
    acc1 += __shfl_xor_sync(0xffffffffu, acc1, 2);
    if (q == 0) {
        out[e0] = 1.f / (1.f + __expf(-(acc0 + sb2)));
        out[e1] = 1.f / (1.f + __expf(-(acc1 + sb2)));
    }
}

extern "C" void kernel_launch(void* const* d_in, const int* in_sizes, int n_in,
                              void* d_out, int out_size) {
    const float* x   = (const float*)d_in[0];
    const int*   src = (const int*)d_in[1];
    const int*   dst = (const int*)d_in[2];
    const float* ea  = (const float*)d_in[3];
    const float* W1  = (const float*)d_in[4];
    const float* b1  = (const float*)d_in[5];
    const float* Wm1 = (const float*)d_in[6];
    const float* bm1 = (const float*)d_in[7];
    const float* Wm2 = (const float*)d_in[8];
    const float* bm2 = (const float*)d_in[9];
    float* out = (float*)d_out;
    (void)in_sizes; (void)n_in; (void)out_size;

    const int NB_SCAN = (N_NODES + 1023) / 1024;  // 49

    // One-time host-side setup (first call is the uncaptured correctness run;
    // no device memory is allocated here).
    static cudaStream_t s_side = nullptr;
    static cudaEvent_t  s_fork = nullptr, s_join = nullptr;
    static void* degi_ptr = nullptr;
    if (!s_side) {
        cudaStreamCreateWithFlags(&s_side, cudaStreamNonBlocking);
        cudaEventCreateWithFlags(&s_fork, cudaEventDisableTiming);
        cudaEventCreateWithFlags(&s_join, cudaEventDisableTiming);
        cudaGetSymbolAddress(&degi_ptr, g_degi);
    }

    // Fork: k_mm1 (independent of graph structure) overlaps the CSR build chain.
    cudaEventRecord(s_fork, 0);
    cudaStreamWaitEvent(s_side, s_fork, 0);
    k_mm1<<<(N_NODES + 63) / 64, 256, 0, s_side>>>(x, W1);
    cudaEventRecord(s_join, s_side);

    // Main stream: degree histogram -> scan -> CSR fill
    cudaMemsetAsync(degi_ptr, 0, N_NODES * sizeof(int), 0);
    k_count<<<(N_EDGES + 255) / 256, 256>>>(dst);
    k_scan1<<<NB_SCAN, 1024>>>();
    k_scan3<<<NB_SCAN, 1024>>>(NB_SCAN);
    k_fill<<<(N_EDGES + 255) / 256, 256>>>(src, dst);

    // Join: k_agg needs both k_mm1 (t) and k_fill (CSR)
    cudaStreamWaitEvent(0, s_join, 0);
    k_agg<<<(N_NODES * 16 + 255) / 256, 256>>>();
    k_mm2<<<(N_NODES + 63) / 64, 256>>>(Wm1, b1, bm1);
    k_edge<<<N_EDGES / 128, 256>>>(src, dst, ea, Wm1, Wm2, bm2, out);
}

// round 12
// speedup vs baseline: 1.8095x; 1.1411x over previous
#include <cuda_runtime.h>
#include <cuda_fp16.h>
#include <math.h>

#define N_NODES 50000
#define N_EDGES 800000

// Scratch (device globals — allocation-free per harness rules)
__device__ int   g_degi[N_NODES];
__device__ int   g_off[N_NODES];
__device__ int   g_cursor[N_NODES];
__device__ int   g_bsum[64];
__device__ int   g_esrc[N_EDGES];       // CSR payload: src node of each in-edge of n
__device__ float g_dinv[N_NODES];
__device__ __align__(16) __half g_th[N_NODES * 64];   // t = x @ W1 (fp16)
__device__ __align__(16) float  g_agg[N_NODES * 64];  // normalized aggregation
__device__ __align__(16) __half g_Ph[N_NODES * 128];  // [A | B] per-node precompute (fp16)

// ---- packed f32x2 helpers (sm_103a FFMA2 — ptxas never auto-fuses these) ----
typedef unsigned long long ull;
__device__ __forceinline__ ull pack2(float v) {
    ull r; asm("mov.b64 %0, {%1,%2};" : "=l"(r) : "f"(v), "f"(v)); return r;
}
__device__ __forceinline__ ull packf2(float2 f) {
    ull r; asm("mov.b64 %0, {%1,%2};" : "=l"(r) : "f"(f.x), "f"(f.y)); return r;
}
__device__ __forceinline__ void unpack2(ull v, float& lo, float& hi) {
    asm("mov.b64 {%0,%1}, %2;" : "=f"(lo), "=f"(hi) : "l"(v));
}
__device__ __forceinline__ void fma2(ull& d, ull a, ull b) {
    asm("fma.rn.f32x2 %0, %1, %2, %0;" : "+l"(d) : "l"(a), "l"(b));
}
__device__ __forceinline__ unsigned int hadd2(unsigned int a, unsigned int b) {
    unsigned int r; asm("add.rn.f16x2 %0, %1, %2;" : "=r"(r) : "r"(a), "r"(b)); return r;
}
__device__ __forceinline__ ull h2tof2(unsigned int h) {
    __half2 hv = *reinterpret_cast<__half2*>(&h);
    float2 f = __half22float2(hv);
    return packf2(f);
}
__device__ __forceinline__ float2 h2f2(unsigned int h) {
    __half2 hv = *reinterpret_cast<__half2*>(&h);
    return __half22float2(hv);
}
__device__ __forceinline__ unsigned int f2h2(float lo, float hi) {
    __half2 p = __floats2half2_rn(lo, hi);
    return *(unsigned int*)&p;
}

__global__ void k_count(const int* __restrict__ dst) {
    int e = blockIdx.x * blockDim.x + threadIdx.x;
    if (e < N_EDGES) atomicAdd(&g_degi[dst[e]], 1);
}

// ---- exclusive prefix scan over g_degi (50000) -> g_off: two small launches ----
__global__ void k_scan1() {
    int tid = threadIdx.x;
    int i = blockIdx.x * 1024 + tid;
    int v = (i < N_NODES) ? g_degi[i] : 0;
    int lane = tid & 31, wid = tid >> 5;
    int s = v;
#pragma unroll
    for (int o = 1; o < 32; o <<= 1) {
        int t = __shfl_up_sync(0xffffffffu, s, o);
        if (lane >= o) s += t;
    }
    __shared__ int ws[32];
    if (lane == 31) ws[wid] = s;
    __syncthreads();
    if (wid == 0) {
        int t = ws[lane];
        int ss = t;
#pragma unroll
        for (int o = 1; o < 32; o <<= 1) {
            int u = __shfl_up_sync(0xffffffffu, ss, o);
            if (lane >= o) ss += u;
        }
        ws[lane] = ss - t;
    }
    __syncthreads();
    int excl = ws[wid] + s - v;
    if (i < N_NODES) g_off[i] = excl;
    if (tid == 1023) g_bsum[blockIdx.x] = ws[31] + s;
}

// scan3: per-block base via redundant smem sum; init cursor; dinv (incl. self loop)
__global__ void k_scan3(int nb) {
    __shared__ int sb[64];
    __shared__ int base_s;
    int tid = threadIdx.x;
    if (tid < 64) sb[tid] = (tid < nb) ? g_bsum[tid] : 0;
    __syncthreads();
    if (tid == 0) {
        int b = 0;
        for (int j = 0; j < (int)blockIdx.x; j++) b += sb[j];
        base_s = b;
    }
    __syncthreads();
    int i = blockIdx.x * 1024 + tid;
    if (i >= N_NODES) return;
    int o = g_off[i] + base_s;
    g_off[i] = o;
    g_cursor[i] = o;
    g_dinv[i] = rsqrtf((float)(g_degi[i] + 1));
}

// CSR fill: store src id directly
__global__ void k_fill(const int* __restrict__ src, const int* __restrict__ dst) {
    int e = blockIdx.x * blockDim.x + threadIdx.x;
    if (e >= N_EDGES) return;
    int pos = atomicAdd(&g_cursor[dst[e]], 1);
    g_esrc[pos] = src[e];
}

// t = x @ W1 (fp16 out) — row-major tiles, float4 fills, 4-k chunked inner loop.
__global__ void k_mm1(const float* __restrict__ x, const float* __restrict__ W1) {
    __shared__ float sW[64 * 64];        // [k][j]
    __shared__ float sx[64 * 68];        // row-major [r][k], pitch 68 floats
    int tid = threadIdx.x;
    int row0 = blockIdx.x * 64;
    const float4* W4 = (const float4*)W1;
    float4* sW4s = (float4*)sW;
    for (int i = tid; i < 1024; i += 256) sW4s[i] = W4[i];
    const float4* x4 = (const float4*)x;
    float4* sx4 = (float4*)sx;
    for (int i = tid; i < 1024; i += 256) {
        int r = i >> 4, q = i & 15;
        int row = row0 + r;
        float4 v = (row < N_NODES) ? x4[row * 16 + q] : make_float4(0.f, 0.f, 0.f, 0.f);
        sx4[r * 17 + q] = v;
    }
    __syncthreads();
    int ty = tid >> 4, tx = tid & 15;
    ull c0a = 0, c0b = 0, c1a = 0, c1b = 0, c2a = 0, c2b = 0, c3a = 0, c3b = 0;
    const ulonglong2* sWu = (const ulonglong2*)sW;
    int rb = ty * 4;
#pragma unroll
    for (int k4 = 0; k4 < 16; k4++) {
        float4 xv0 = *(const float4*)&sx[(rb + 0) * 68 + k4 * 4];
        float4 xv1 = *(const float4*)&sx[(rb + 1) * 68 + k4 * 4];
        float4 xv2 = *(const float4*)&sx[(rb + 2) * 68 + k4 * 4];
        float4 xv3 = *(const float4*)&sx[(rb + 3) * 68 + k4 * 4];
        const float* p0 = &xv0.x;
        const float* p1 = &xv1.x;
        const float* p2 = &xv2.x;
        const float* p3 = &xv3.x;
#pragma unroll
        for (int j = 0; j < 4; j++) {
            int k = k4 * 4 + j;
            ulonglong2 w = sWu[k * 16 + tx];
            ull X0 = pack2(p0[j]), X1 = pack2(p1[j]), X2 = pack2(p2[j]), X3 = pack2(p3[j]);
            fma2(c0a, X0, w.x); fma2(c0b, X0, w.y);
            fma2(c1a, X1, w.x); fma2(c1b, X1, w.y);
            fma2(c2a, X2, w.x); fma2(c2b, X2, w.y);
            fma2(c3a, X3, w.x); fma2(c3b, X3, w.y);
        }
    }
    uint2* th2 = (uint2*)g_th;   // 16 uint2 per node row (64 halves)
    int row = row0 + rb;
    float lo, hi;
    uint2 u;
    unpack2(c0a, lo, hi); u.x = f2h2(lo, hi);
    unpack2(c0b, lo, hi); u.y = f2h2(lo, hi);
    if (row + 0 < N_NODES) th2[(row + 0) * 16 + tx] = u;
    unpack2(c1a, lo, hi); u.x = f2h2(lo, hi);
    unpack2(c1b, lo, hi); u.y = f2h2(lo, hi);
    if (row + 1 < N_NODES) th2[(row + 1) * 16 + tx] = u;
    unpack2(c2a, lo, hi); u.x = f2h2(lo, hi);
    unpack2(c2b, lo, hi); u.y = f2h2(lo, hi);
    if (row + 2 < N_NODES) th2[(row + 2) * 16 + tx] = u;
    unpack2(c3a, lo, hi); u.x = f2h2(lo, hi);
    unpack2(c3b, lo, hi); u.y = f2h2(lo, hi);
    if (row + 3 < N_NODES) th2[(row + 3) * 16 + tx] = u;
}

// CSR gather-reduce over fp16 t, no atomics. 16 threads/node, uint2 (4 cols) each.
__global__ void k_agg() {
    unsigned int gid = blockIdx.x * blockDim.x + threadIdx.x;
    unsigned int n = gid >> 4;
    int c = gid & 15;
    if (n >= N_NODES) return;
    const uint2* t2 = (const uint2*)g_th;
    float dn = g_dinv[n];
    uint2 u = t2[n * 16 + c];
    float2 s01 = h2f2(u.x), s23 = h2f2(u.y);
    float w2 = dn * dn;
    float4 acc = make_float4(s01.x * w2, s01.y * w2, s23.x * w2, s23.y * w2);
    int beg = g_off[n];
    int end = beg + g_degi[n];
#pragma unroll 4
    for (int j = beg; j < end; j++) {
        int s = g_esrc[j];             // broadcast across the 16-thread group
        float w = dn * g_dinv[s];
        uint2 uu = t2[s * 16 + c];
        float2 a01 = h2f2(uu.x), a23 = h2f2(uu.y);
        acc.x += a01.x * w; acc.y += a01.y * w;
        acc.z += a23.x * w; acc.w += a23.y * w;
    }
    ((float4*)g_agg)[n * 16 + c] = acc;
}

// h = relu(agg + b1); P = [h@Wm1[0:64]+bm1 | h@Wm1[64:128]] stored fp16.
// Tensor-core version: 8 warps/block, each owns a 16-row x 64-col output tile.
// h tile fp16 in smem (pitch 36 words -> conflict-free fragment loads);
// Wm1 prebuilt as B fragments (uint2 per (kstep, ntile, lane)).
__global__ void k_mm2(const float* __restrict__ Wm1, const float* __restrict__ b1,
                      const float* __restrict__ bm1) {
    __shared__ unsigned short sH[64 * 72];   // h fp16, pitch 72 halves = 36 words
    __shared__ uint2 sB[4 * 16 * 32];        // B frags: [kt][ntile][lane] = 16KB
    __shared__ float sbm[64];
    int tid = threadIdx.x;
    int row0 = blockIdx.x * 64;

    // --- h tile: relu(agg + b1) -> fp16 smem ---
    {
        const float4* agg4 = (const float4*)g_agg;
        const float4* b14 = (const float4*)b1;
        unsigned int* H32 = (unsigned int*)sH;
        for (int i = tid; i < 1024; i += 256) {
            int r = i >> 4, qd = i & 15;
            int row = row0 + r;
            unsigned int w0 = 0, w1 = 0;
            if (row < N_NODES) {
                float4 a = agg4[row * 16 + qd];
                float4 b = b14[qd];
                float vx = fmaxf(a.x + b.x, 0.f), vy = fmaxf(a.y + b.y, 0.f);
                float vz = fmaxf(a.z + b.z, 0.f), vw = fmaxf(a.w + b.w, 0.f);
                w0 = f2h2(vx, vy); w1 = f2h2(vz, vw);
            }
            H32[r * 36 + qd * 2 + 0] = w0;
            H32[r * 36 + qd * 2 + 1] = w1;
        }
    }
    // --- B fragments: effective weight We[k][col] = col<64 ? Wm1[k][col] : Wm1[64+k][col-64] ---
    for (int i = tid; i < 2048; i += 256) {
        int kt = i >> 9, rem = i & 511;
        int nt = rem >> 5, lane2 = rem & 31;
        int gg = lane2 >> 2, qq = lane2 & 3;
        int colg = nt * 8 + gg;
        int rbase = (colg < 64) ? 0 : 64;
        int col = colg & 63;
        int k0 = kt * 16 + 2 * qq;
        uint2 v;
        v.x = f2h2(Wm1[(rbase + k0) * 64 + col],     Wm1[(rbase + k0 + 1) * 64 + col]);
        v.y = f2h2(Wm1[(rbase + k0 + 8) * 64 + col], Wm1[(rbase + k0 + 9) * 64 + col]);
        sB[(kt * 16 + nt) * 32 + lane2] = v;
    }
    if (tid < 64) sbm[tid] = bm1[tid];
    __syncthreads();

    int lane = tid & 31, w = tid >> 5;
    int g = lane >> 2, q = lane & 3;
    int rt = w & 3, ch = w >> 2;      // row tile (16 rows), col half (64 cols)
    int rloc = rt * 16;
    float acc[8][4];
#pragma unroll
    for (int j = 0; j < 8; j++) { acc[j][0] = acc[j][1] = acc[j][2] = acc[j][3] = 0.f; }

    const unsigned int* H32 = (const unsigned int*)sH;
#pragma unroll
    for (int kt = 0; kt < 4; kt++) {
        int base = (rloc + g) * 36 + kt * 8;
        unsigned int a0 = H32[base + q];
        unsigned int a1 = H32[base + 8 * 36 + q];
        unsigned int a2 = H32[base + q + 4];
        unsigned int a3 = H32[base + 8 * 36 + q + 4];
#pragma unroll
        for (int j = 0; j < 8; j++) {
            int nt = ch * 8 + j;
            uint2 b = sB[(kt * 16 + nt) * 32 + lane];
            asm volatile(
                "mma.sync.aligned.m16n8k16.row.col.f32.f16.f16.f32 "
                "{%0,%1,%2,%3}, {%4,%5,%6,%7}, {%8,%9}, {%0,%1,%2,%3};"
                : "+f"(acc[j][0]), "+f"(acc[j][1]), "+f"(acc[j][2]), "+f"(acc[j][3])
                : "r"(a0), "r"(a1), "r"(a2), "r"(a3), "r"(b.x), "r"(b.y));
        }
    }

    // --- epilogue: +bm1 on A-half cols, fp16 pack, store to g_Ph ---
    unsigned int* Ph32 = (unsigned int*)g_Ph;   // 64 half2-words per node row
    int row_g0 = row0 + rloc + g;
    int row_g8 = row_g0 + 8;
#pragma unroll
    for (int j = 0; j < 8; j++) {
        int nt = ch * 8 + j;
        float c0 = acc[j][0], c1 = acc[j][1], c2 = acc[j][2], c3 = acc[j][3];
        if (ch == 0) {                 // cols nt*8+2q < 64: add bm1
            float2 bb = *(const float2*)&sbm[nt * 8 + 2 * q];
            c0 += bb.x; c1 += bb.y; c2 += bb.x; c3 += bb.y;
        }
        int cw = nt * 4 + q;
        if (row_g0 < N_NODES) Ph32[row_g0 * 64 + cw] = f2h2(c0, c1);
        if (row_g8 < N_NODES) Ph32[row_g8 * 64 + cw] = f2h2(c2, c3);
    }
}

// per-edge via tensor cores: G = ea@We on HMMA (m16n8k16), epilogue in-register.
// Each warp owns 16 edges; block = 256 threads = 8 warps = 128 edges; grid = 6250.
__global__ void k_edge(const int* __restrict__ src, const int* __restrict__ dst,
                       const float* __restrict__ ea, const float* __restrict__ Wm1,
                       const float* __restrict__ Wm2, const float* __restrict__ bm2,
                       float* __restrict__ out) {
    __shared__ __align__(16) unsigned short sEA[128 * 16];   // ea tile fp16, pitch 16 halves
    __shared__ unsigned int sB0[8 * 32], sB1[8 * 32];        // B fragments per (tile, lane)
    __shared__ float sW2[64];
    __shared__ float sb2;
    int tid = threadIdx.x;
    int lane = tid & 31, w = tid >> 5;
    int g = lane >> 2, q = lane & 3;
    // --- B fragments for We = Wm1 rows 128..143 (k=16 x n=64), col-tile = tid>>5 ---
    {
        int coln = (tid >> 5) * 8 + g;     // n-column for this (tile, lane)
        int k0 = 2 * q;
        sB0[tid] = f2h2(Wm1[(128 + k0) * 64 + coln],     Wm1[(128 + k0 + 1) * 64 + coln]);
        sB1[tid] = f2h2(Wm1[(128 + k0 + 8) * 64 + coln], Wm1[(128 + k0 + 9) * 64 + coln]);
    }
    if (tid < 64) sW2[tid] = Wm2[tid];
    if (tid == 0) sb2 = bm2[0];
    // --- ea -> smem fp16: thread loads half a row (8 floats) ---
    {
        int eloc = tid >> 1, part = tid & 1;
        size_t e = (size_t)blockIdx.x * 128 + eloc;
        const float4* ea4 = (const float4*)(ea + e * 16) + part * 2;
        float4 v0 = ea4[0], v1 = ea4[1];
        unsigned int* d16 = (unsigned int*)&sEA[eloc * 16 + part * 8];
        d16[0] = f2h2(v0.x, v0.y); d16[1] = f2h2(v0.z, v0.w);
        d16[2] = f2h2(v1.x, v1.y); d16[3] = f2h2(v1.z, v1.w);
    }
    __syncthreads();
    // --- per-warp: 16 edges [wbase, wbase+16) ---
    int wbase = w * 16;
    int r0 = wbase + g, r1 = wbase + g + 8;          // this thread's two edge rows
    unsigned int ebase = blockIdx.x * 128;
    int e0 = ebase + r0, e1 = ebase + r1;
    int s0 = src[e0], d0n = dst[e0];
    int s1 = src[e1], d1n = dst[e1];
    // A fragments (rows r0/r1 of ea tile, halves 2q..2q+1 and 2q+8..2q+9)
    const unsigned int* EA32 = (const unsigned int*)sEA;   // 8 words per edge row
    unsigned int a0 = EA32[r0 * 8 + q];
    unsigned int a1 = EA32[r1 * 8 + q];
    unsigned int a2 = EA32[r0 * 8 + q + 4];
    unsigned int a3 = EA32[r1 * 8 + q + 4];
    const unsigned int* Ph32 = (const unsigned int*)g_Ph;  // 64 half2-words per node
    float acc0 = 0.f, acc1 = 0.f;
#pragma unroll
    for (int j = 0; j < 8; j++) {
        float c0 = 0.f, c1 = 0.f, c2 = 0.f, c3 = 0.f;
        asm volatile(
            "mma.sync.aligned.m16n8k16.row.col.f32.f16.f16.f32 "
            "{%0,%1,%2,%3}, {%4,%5,%6,%7}, {%8,%9}, {%0,%1,%2,%3};"
            : "+f"(c0), "+f"(c1), "+f"(c2), "+f"(c3)
            : "r"(a0), "r"(a1), "r"(a2), "r"(a3),
              "r"(sB0[j * 32 + lane]), "r"(sB1[j * 32 + lane]));
        // cols for this thread: jc = j*8 + 2q, jc+1  -> half2 word j*4+q
        int cw = j * 4 + q;
        unsigned int pa0 = Ph32[s0 * 64 + cw];          // A half (cols 0..63)
        unsigned int pb0 = Ph32[d0n * 64 + 32 + cw];    // B half (cols 64..127)
        unsigned int pa1 = Ph32[s1 * 64 + cw];
        unsigned int pb1 = Ph32[d1n * 64 + 32 + cw];
        float2 h0 = h2f2(hadd2(pa0, pb0));
        float2 h1 = h2f2(hadd2(pa1, pb1));
        c0 = fmaxf(c0 + h0.x, 0.f); c1 = fmaxf(c1 + h0.y, 0.f);
        c2 = fmaxf(c2 + h1.x, 0.f); c3 = fmaxf(c3 + h1.y, 0.f);
        float2 w2v = *(const float2*)&sW2[j * 8 + 2 * q];
        acc0 += c0 * w2v.x + c1 * w2v.y;
        acc1 += c2 * w2v.x + c3 * w2v.y;
    }
    // reduce across the 4 lanes sharing each edge row (lanes g*4 .. g*4+3)
    acc0 += __shfl_xor_sync(0xffffffffu, acc0, 1);
    acc0 += __shfl_xor_sync(0xffffffffu, acc0, 2);
    acc1 += __shfl_xor_sync(0xffffffffu, acc1, 1);
    acc1 += __shfl_xor_sync(0xffffffffu, acc1, 2);
    if (q == 0) {
        out[e0] = 1.f / (1.f + __expf(-(acc0 + sb2)));
        out[e1] = 1.f / (1.f + __expf(-(acc1 + sb2)));
    }
}

extern "C" void kernel_launch(void* const* d_in, const int* in_sizes, int n_in,
                              void* d_out, int out_size) {
    const float* x   = (const float*)d_in[0];
    const int*   src = (const int*)d_in[1];
    const int*   dst = (const int*)d_in[2];
    const float* ea  = (const float*)d_in[3];
    const float* W1  = (const float*)d_in[4];
    const float* b1  = (const float*)d_in[5];
    const float* Wm1 = (const float*)d_in[6];
    const float* bm1 = (const float*)d_in[7];
    const float* Wm2 = (const float*)d_in[8];
    const float* bm2 = (const float*)d_in[9];
    float* out = (float*)d_out;
    (void)in_sizes; (void)n_in; (void)out_size;

    const int NB_SCAN = (N_NODES + 1023) / 1024;  // 49

    // One-time host-side setup (first call is the uncaptured correctness run;
    // no device memory is allocated here).
    static cudaStream_t s_side = nullptr;
    static cudaEvent_t  s_fork = nullptr, s_join = nullptr;
    static void* degi_ptr = nullptr;
    if (!s_side) {
        cudaStreamCreateWithFlags(&s_side, cudaStreamNonBlocking);
        cudaEventCreateWithFlags(&s_fork, cudaEventDisableTiming);
        cudaEventCreateWithFlags(&s_join, cudaEventDisableTiming);
        cudaGetSymbolAddress(&degi_ptr, g_degi);
    }

    // Fork: k_mm1 (independent of graph structure) overlaps the CSR build chain.
    cudaEventRecord(s_fork, 0);
    cudaStreamWaitEvent(s_side, s_fork, 0);
    k_mm1<<<(N_NODES + 63) / 64, 256, 0, s_side>>>(x, W1);
    cudaEventRecord(s_join, s_side);

    // Main stream: degree histogram -> scan -> CSR fill
    cudaMemsetAsync(degi_ptr, 0, N_NODES * sizeof(int), 0);
    k_count<<<(N_EDGES + 255) / 256, 256>>>(dst);
    k_scan1<<<NB_SCAN, 1024>>>();
    k_scan3<<<NB_SCAN, 1024>>>(NB_SCAN);
    k_fill<<<(N_EDGES + 255) / 256, 256>>>(src, dst);

    // Join: k_agg needs both k_mm1 (t) and k_fill (CSR)
    cudaStreamWaitEvent(0, s_join, 0);
    k_agg<<<(N_NODES * 16 + 255) / 256, 256>>>();
    k_mm2<<<(N_NODES + 63) / 64, 256>>>(Wm1, b1, bm1);
    k_edge<<<N_EDGES / 128, 256>>>(src, dst, ea, Wm1, Wm2, bm2, out);
}